// round 1
// baseline (speedup 1.0000x reference)
#include <cuda_runtime.h>

#define NN 100000
#define EE 300000
#define GG 4000

// ---------------- scratch (device globals; no allocation) ----------------
__device__ __align__(16) float g_h1[NN * 512];   // layer1 projected features [N,4,128]
__device__ __align__(16) float g_as1[NN * 4];    // alpha_src layer1 [N,4]
__device__ __align__(16) float g_ad1[NN * 4];    // alpha_dst layer1 [N,4]
__device__ __align__(16) float g_o1[NN * 512];   // layer1 output (post ELU) = layer2 input
__device__ __align__(16) float g_h2[NN * 128];   // layer2 projected features [N,128]
__device__ float g_as2[NN];
__device__ float g_ad2[NN];
__device__ __align__(16) float g_o2[NN * 128];   // layer2 output (post ELU)
__device__ int   g_deg[NN];
__device__ int   g_rowptr[NN + 1];
__device__ int   g_cursor[NN];
__device__ int   g_col[EE];                      // src node per CSR slot (sorted by dst)
__device__ float g_cnt[GG];

__device__ __forceinline__ float lrelu(float x) { return x > 0.f ? x : 0.2f * x; }
__device__ __forceinline__ float eluf(float x)  { return x > 0.f ? x : (__expf(x) - 1.f); }

// ---------------- CSR build ----------------
__global__ void k_zero_deg() {
    int i = blockIdx.x * blockDim.x + threadIdx.x;
    if (i < NN) g_deg[i] = 0;
}

__global__ void k_count(const int* __restrict__ ei) {
    int e = blockIdx.x * blockDim.x + threadIdx.x;
    if (e < EE) atomicAdd(&g_deg[ei[EE + e]], 1);
}

// single-block scan: each thread handles CH contiguous elements, shuffle scan across block
__global__ void k_scan() {
    const int CH = 16;
    __shared__ int warp_s[32];
    int tid = threadIdx.x, lane = tid & 31, w = tid >> 5;
    int offset = 0;
    for (int base = 0; base < NN; base += 1024 * CH) {
        int i0 = base + tid * CH;
        int v[CH];
        int tot = 0;
#pragma unroll
        for (int c = 0; c < CH; c++) {
            int idx = i0 + c;
            v[c] = (idx < NN) ? g_deg[idx] : 0;
            tot += v[c];
        }
        int x = tot;
#pragma unroll
        for (int o = 1; o < 32; o <<= 1) {
            int t = __shfl_up_sync(0xffffffffu, x, o);
            if (lane >= o) x += t;
        }
        if (lane == 31) warp_s[w] = x;
        __syncthreads();
        if (w == 0) {
            int y = warp_s[lane];
#pragma unroll
            for (int o = 1; o < 32; o <<= 1) {
                int t = __shfl_up_sync(0xffffffffu, y, o);
                if (lane >= o) y += t;
            }
            warp_s[lane] = y;
        }
        __syncthreads();
        int excl = x - tot + ((w > 0) ? warp_s[w - 1] : 0) + offset;
        int run = excl;
#pragma unroll
        for (int c = 0; c < CH; c++) {
            int idx = i0 + c;
            if (idx < NN) {
                g_cursor[idx] = run;
                run += v[c];
                g_rowptr[idx + 1] = run;
            }
        }
        int total = warp_s[31];
        __syncthreads();   // protect warp_s before next iteration
        offset += total;
    }
    if (tid == 0) g_rowptr[0] = 0;
}

__global__ void k_fill(const int* __restrict__ ei) {
    int e = blockIdx.x * blockDim.x + threadIdx.x;
    if (e < EE) {
        int s = ei[e], d = ei[EE + e];
        int p = atomicAdd(&g_cursor[d], 1);
        g_col[p] = s;
    }
}

// ---------------- layer 1 projection + attention coefficients ----------------
// h1 = x @ W1 ; as1[n,h] = <h1[n,h,:], a_src1[h,:]> ; ad1 likewise
__global__ void k_proj1(const float* __restrict__ x, const float* __restrict__ W1,
                        const float* __restrict__ a_src1, const float* __restrict__ a_dst1) {
    __shared__ float sW[9 * 512];
    __shared__ float wsum[4][8];
    int tid = threadIdx.x;
    for (int i = tid; i < 9 * 512; i += 128) sW[i] = W1[i];
    float asr[4], adr[4];
#pragma unroll
    for (int h = 0; h < 4; h++) {
        asr[h] = a_src1[h * 128 + tid];
        adr[h] = a_dst1[h * 128 + tid];
    }
    __syncthreads();
    int n0 = blockIdx.x * 32;
    for (int u = 0; u < 32; u++) {
        int n = n0 + u;
        if (n >= NN) return;
        float xr[9];
#pragma unroll
        for (int k = 0; k < 9; k++) xr[k] = __ldg(&x[n * 9 + k]);
        float p[8];
#pragma unroll
        for (int h = 0; h < 4; h++) {
            float v = 0.f;
#pragma unroll
            for (int k = 0; k < 9; k++) v = fmaf(xr[k], sW[k * 512 + h * 128 + tid], v);
            g_h1[(n * 4 + h) * 128 + tid] = v;
            p[h] = v * asr[h];
            p[4 + h] = v * adr[h];
        }
#pragma unroll
        for (int q = 0; q < 8; q++)
#pragma unroll
            for (int o = 16; o > 0; o >>= 1) p[q] += __shfl_down_sync(0xffffffffu, p[q], o);
        int w = tid >> 5;
        if ((tid & 31) == 0) {
#pragma unroll
            for (int q = 0; q < 8; q++) wsum[w][q] = p[q];
        }
        __syncthreads();
        if (tid < 8) {
            float s = wsum[0][tid] + wsum[1][tid] + wsum[2][tid] + wsum[3][tid];
            if (tid < 4) g_as1[n * 4 + tid] = s;
            else g_ad1[n * 4 + (tid - 4)] = s;
        }
        __syncthreads();
    }
}

// ---------------- layer 1 attention aggregation (block per dst node, H=4) ----------------
__global__ void k_agg1(const float* __restrict__ b1) {
    int n = blockIdx.x, tid = threadIdx.x;
    const float4* as4 = (const float4*)g_as1;
    float4 adv = ((const float4*)g_ad1)[n];
    float4 a0 = as4[n];
    float l0 = lrelu(a0.x + adv.x), l1 = lrelu(a0.y + adv.y);
    float l2 = lrelu(a0.z + adv.z), l3 = lrelu(a0.w + adv.w);
    float m0 = l0, m1 = l1, m2 = l2, m3 = l3;
    int beg = g_rowptr[n], end = g_rowptr[n + 1];
    for (int j = beg; j < end; j++) {
        float4 a = as4[g_col[j]];
        m0 = fmaxf(m0, lrelu(a.x + adv.x));
        m1 = fmaxf(m1, lrelu(a.y + adv.y));
        m2 = fmaxf(m2, lrelu(a.z + adv.z));
        m3 = fmaxf(m3, lrelu(a.w + adv.w));
    }
    float z0 = __expf(l0 - m0), z1 = __expf(l1 - m1);
    float z2 = __expf(l2 - m2), z3 = __expf(l3 - m3);
    const float* hn = g_h1 + n * 512;
    float acc0 = z0 * hn[tid];
    float acc1 = z1 * hn[128 + tid];
    float acc2 = z2 * hn[256 + tid];
    float acc3 = z3 * hn[384 + tid];
    for (int j = beg; j < end; j++) {
        int s = g_col[j];
        float4 a = as4[s];
        float e0 = __expf(lrelu(a.x + adv.x) - m0);
        float e1 = __expf(lrelu(a.y + adv.y) - m1);
        float e2 = __expf(lrelu(a.z + adv.z) - m2);
        float e3 = __expf(lrelu(a.w + adv.w) - m3);
        const float* hs = g_h1 + s * 512;
        acc0 = fmaf(e0, hs[tid], acc0);
        acc1 = fmaf(e1, hs[128 + tid], acc1);
        acc2 = fmaf(e2, hs[256 + tid], acc2);
        acc3 = fmaf(e3, hs[384 + tid], acc3);
        z0 += e0; z1 += e1; z2 += e2; z3 += e3;
    }
    float* o = g_o1 + n * 512;
    o[tid]       = eluf(acc0 / (z0 + 1e-16f) + b1[tid]);
    o[128 + tid] = eluf(acc1 / (z1 + 1e-16f) + b1[128 + tid]);
    o[256 + tid] = eluf(acc2 / (z2 + 1e-16f) + b1[256 + tid]);
    o[384 + tid] = eluf(acc3 / (z3 + 1e-16f) + b1[384 + tid]);
}

// ---------------- layer 2 projection: g_h2 = g_o1[100000,512] @ W2[512,128] ----------------
__global__ void k_gemm2(const float* __restrict__ B) {
    __shared__ float As[32][65];
    __shared__ float Bs[32][128];
    int tid = threadIdx.x;
    int tx = tid & 31, ty = tid >> 5;
    int m0 = blockIdx.x * 64;
    float acc[8][4];
#pragma unroll
    for (int i = 0; i < 8; i++)
#pragma unroll
        for (int j = 0; j < 4; j++) acc[i][j] = 0.f;
    const float* A = g_o1;
    for (int k0 = 0; k0 < 512; k0 += 32) {
        // A tile: 64 rows x 32 cols, stored transposed (As[k][m]); 8 floats/thread
        {
            int e = tid * 8;
            int r = e >> 5;
            int c = e & 31;
            int row = m0 + r;
            float4 v0 = make_float4(0.f, 0.f, 0.f, 0.f), v1 = v0;
            if (row < NN) {
                const float4* p = (const float4*)(A + row * 512 + k0 + c);
                v0 = p[0];
                v1 = p[1];
            }
            As[c + 0][r] = v0.x; As[c + 1][r] = v0.y; As[c + 2][r] = v0.z; As[c + 3][r] = v0.w;
            As[c + 4][r] = v1.x; As[c + 5][r] = v1.y; As[c + 6][r] = v1.z; As[c + 7][r] = v1.w;
        }
        // B tile: 32 x 128 row-major; 16 floats/thread
        {
            int rb = tid >> 3;
            int cb = (tid & 7) * 16;
            const float4* pb = (const float4*)(B + (k0 + rb) * 128 + cb);
            float4 b0 = pb[0], b1 = pb[1], b2 = pb[2], b3 = pb[3];
            float4* db = (float4*)&Bs[rb][cb];
            db[0] = b0; db[1] = b1; db[2] = b2; db[3] = b3;
        }
        __syncthreads();
#pragma unroll
        for (int k = 0; k < 32; k++) {
            float a[8];
#pragma unroll
            for (int i = 0; i < 8; i++) a[i] = As[k][ty * 8 + i];
            float4 bv = *(const float4*)&Bs[k][tx * 4];
#pragma unroll
            for (int i = 0; i < 8; i++) {
                acc[i][0] = fmaf(a[i], bv.x, acc[i][0]);
                acc[i][1] = fmaf(a[i], bv.y, acc[i][1]);
                acc[i][2] = fmaf(a[i], bv.z, acc[i][2]);
                acc[i][3] = fmaf(a[i], bv.w, acc[i][3]);
            }
        }
        __syncthreads();
    }
#pragma unroll
    for (int i = 0; i < 8; i++) {
        int row = m0 + ty * 8 + i;
        if (row < NN) {
            float4 v = make_float4(acc[i][0], acc[i][1], acc[i][2], acc[i][3]);
            *((float4*)(g_h2 + row * 128 + tx * 4)) = v;
        }
    }
}

// ---------------- layer 2 attention coefficients ----------------
__global__ void k_alpha2(const float* __restrict__ a_src2, const float* __restrict__ a_dst2) {
    int n = blockIdx.x, tid = threadIdx.x;
    float v = g_h2[n * 128 + tid];
    float ps = v * a_src2[tid];
    float pd = v * a_dst2[tid];
#pragma unroll
    for (int o = 16; o > 0; o >>= 1) {
        ps += __shfl_down_sync(0xffffffffu, ps, o);
        pd += __shfl_down_sync(0xffffffffu, pd, o);
    }
    __shared__ float s[8];
    int w = tid >> 5;
    if ((tid & 31) == 0) { s[w] = ps; s[4 + w] = pd; }
    __syncthreads();
    if (tid == 0) g_as2[n] = s[0] + s[1] + s[2] + s[3];
    if (tid == 1) g_ad2[n] = s[4] + s[5] + s[6] + s[7];
}

// ---------------- layer 2 attention aggregation (H=1) ----------------
__global__ void k_agg2(const float* __restrict__ b2) {
    int n = blockIdx.x, tid = threadIdx.x;
    float adn = g_ad2[n];
    float l = lrelu(g_as2[n] + adn);
    float m = l;
    int beg = g_rowptr[n], end = g_rowptr[n + 1];
    for (int j = beg; j < end; j++)
        m = fmaxf(m, lrelu(g_as2[g_col[j]] + adn));
    float z = __expf(l - m);
    float acc = z * g_h2[n * 128 + tid];
    for (int j = beg; j < end; j++) {
        int s = g_col[j];
        float e = __expf(lrelu(g_as2[s] + adn) - m);
        z += e;
        acc = fmaf(e, g_h2[s * 128 + tid], acc);
    }
    g_o2[n * 128 + tid] = eluf(acc / (z + 1e-16f) + b2[tid]);
}

// ---------------- global mean pool ----------------
__global__ void k_pool_zero(float* __restrict__ out) {
    int i = blockIdx.x * blockDim.x + threadIdx.x;
    if (i < GG * 128) out[i] = 0.f;
    if (i < GG) g_cnt[i] = 0.f;
}

__global__ void k_pool_acc(const int* __restrict__ batch, float* __restrict__ out) {
    int n = blockIdx.x, tid = threadIdx.x;
    int g = batch[n];
    atomicAdd(&out[g * 128 + tid], g_o2[n * 128 + tid]);
    if (tid == 0) atomicAdd(&g_cnt[g], 1.f);
}

__global__ void k_pool_div(float* __restrict__ out) {
    int g = blockIdx.x, tid = threadIdx.x;
    out[g * 128 + tid] /= fmaxf(g_cnt[g], 1.f);
}

// ---------------- launcher ----------------
extern "C" void kernel_launch(void* const* d_in, const int* in_sizes, int n_in,
                              void* d_out, int out_size) {
    const float* x       = (const float*)d_in[0];
    const int*   ei      = (const int*)d_in[1];
    const int*   batch   = (const int*)d_in[2];
    const float* W1      = (const float*)d_in[3];
    const float* a_src1  = (const float*)d_in[4];
    const float* a_dst1  = (const float*)d_in[5];
    const float* b1      = (const float*)d_in[6];
    const float* W2      = (const float*)d_in[7];
    const float* a_src2  = (const float*)d_in[8];
    const float* a_dst2  = (const float*)d_in[9];
    const float* b2      = (const float*)d_in[10];
    float* out = (float*)d_out;

    k_zero_deg<<<(NN + 255) / 256, 256>>>();
    k_count<<<(EE + 255) / 256, 256>>>(ei);
    k_scan<<<1, 1024>>>();
    k_fill<<<(EE + 255) / 256, 256>>>(ei);

    k_proj1<<<(NN + 31) / 32, 128>>>(x, W1, a_src1, a_dst1);
    k_agg1<<<NN, 128>>>(b1);

    k_gemm2<<<(NN + 63) / 64, 256>>>(W2);
    k_alpha2<<<NN, 128>>>(a_src2, a_dst2);
    k_agg2<<<NN, 128>>>(b2);

    k_pool_zero<<<(GG * 128 + 255) / 256, 256>>>(out);
    k_pool_acc<<<NN, 128>>>(batch, out);
    k_pool_div<<<GG, 128>>>(out);
}

// round 3
// speedup vs baseline: 1.3186x; 1.3186x over previous
#include <cuda_runtime.h>
#include <cuda_bf16.h>
#include <cstdint>

#define NN 100000
#define EE 300000
#define GG 4000

// ---------------- scratch (device globals; no allocation) ----------------
__device__ __align__(16) float g_h1[NN * 512];            // layer1 projected features [N,4,128]
__device__ __align__(16) float g_as1[NN * 4];
__device__ __align__(16) float g_ad1[NN * 4];
__device__ __align__(16) __nv_bfloat16 g_a_hi[NN * 512];  // layer1 output hi (GEMM A)
__device__ __align__(16) __nv_bfloat16 g_a_lo[NN * 512];  // layer1 output lo
__device__ __align__(16) __nv_bfloat16 g_w2t_hi[128 * 512]; // W2^T hi  [n=128][k=512]
__device__ __align__(16) __nv_bfloat16 g_w2t_lo[128 * 512]; // W2^T lo
__device__ __align__(16) float g_h2[NN * 128];            // layer2 projected features
__device__ float g_as2[NN];
__device__ float g_ad2[NN];
__device__ int   g_deg[NN];
__device__ int   g_rowptr[NN + 1];
__device__ int   g_cursor[NN];
__device__ int   g_col[EE];
__device__ float g_cnt[GG];

__device__ __forceinline__ float lrelu(float x) { return x > 0.f ? x : 0.2f * x; }
__device__ __forceinline__ float eluf(float x)  { return x > 0.f ? x : (__expf(x) - 1.f); }

__device__ __forceinline__ uint32_t smem_to_u32(const void* p) {
    uint32_t a;
    asm("{ .reg .u64 t; cvta.to.shared.u64 t, %1; cvt.u32.u64 %0, t; }" : "=r"(a) : "l"(p));
    return a;
}

#define LDSM_X4(r0, r1, r2, r3, addr) \
    asm volatile("ldmatrix.sync.aligned.m8n8.x4.shared.b16 {%0,%1,%2,%3}, [%4];" \
        : "=r"(r0), "=r"(r1), "=r"(r2), "=r"(r3) : "r"(addr))

__device__ __forceinline__ void mma16816(float* d, uint32_t a0, uint32_t a1, uint32_t a2,
                                         uint32_t a3, uint32_t b0, uint32_t b1) {
    asm volatile(
        "mma.sync.aligned.m16n8k16.row.col.f32.bf16.bf16.f32 "
        "{%0,%1,%2,%3}, {%4,%5,%6,%7}, {%8,%9}, {%0,%1,%2,%3};"
        : "+f"(d[0]), "+f"(d[1]), "+f"(d[2]), "+f"(d[3])
        : "r"(a0), "r"(a1), "r"(a2), "r"(a3), "r"(b0), "r"(b1));
}

// ---------------- CSR build ----------------
__global__ void k_zero_deg() {
    int i = blockIdx.x * blockDim.x + threadIdx.x;
    if (i < NN) g_deg[i] = 0;
}

__global__ void k_count(const int* __restrict__ ei) {
    int e = blockIdx.x * blockDim.x + threadIdx.x;
    if (e < EE) atomicAdd(&g_deg[ei[EE + e]], 1);
}

__global__ void k_scan() {
    const int CH = 16;
    __shared__ int warp_s[32];
    int tid = threadIdx.x, lane = tid & 31, w = tid >> 5;
    int offset = 0;
    for (int base = 0; base < NN; base += 1024 * CH) {
        int i0 = base + tid * CH;
        int v[CH];
        int tot = 0;
#pragma unroll
        for (int c = 0; c < CH; c++) {
            int idx = i0 + c;
            v[c] = (idx < NN) ? g_deg[idx] : 0;
            tot += v[c];
        }
        int x = tot;
#pragma unroll
        for (int o = 1; o < 32; o <<= 1) {
            int t = __shfl_up_sync(0xffffffffu, x, o);
            if (lane >= o) x += t;
        }
        if (lane == 31) warp_s[w] = x;
        __syncthreads();
        if (w == 0) {
            int y = warp_s[lane];
#pragma unroll
            for (int o = 1; o < 32; o <<= 1) {
                int t = __shfl_up_sync(0xffffffffu, y, o);
                if (lane >= o) y += t;
            }
            warp_s[lane] = y;
        }
        __syncthreads();
        int excl = x - tot + ((w > 0) ? warp_s[w - 1] : 0) + offset;
        int run = excl;
#pragma unroll
        for (int c = 0; c < CH; c++) {
            int idx = i0 + c;
            if (idx < NN) {
                g_cursor[idx] = run;
                run += v[c];
                g_rowptr[idx + 1] = run;
            }
        }
        int total = warp_s[31];
        __syncthreads();
        offset += total;
    }
    if (tid == 0) g_rowptr[0] = 0;
}

__global__ void k_fill(const int* __restrict__ ei) {
    int e = blockIdx.x * blockDim.x + threadIdx.x;
    if (e < EE) {
        int s = ei[e], d = ei[EE + e];
        int p = atomicAdd(&g_cursor[d], 1);
        g_col[p] = s;
    }
}

// ---------------- layer 1 projection + attention coefficients ----------------
__global__ void k_proj1(const float* __restrict__ x, const float* __restrict__ W1,
                        const float* __restrict__ a_src1, const float* __restrict__ a_dst1) {
    __shared__ float sW[9 * 512];
    __shared__ float wsum[4][8];
    int tid = threadIdx.x;
    for (int i = tid; i < 9 * 512; i += 128) sW[i] = W1[i];
    float asr[4], adr[4];
#pragma unroll
    for (int h = 0; h < 4; h++) {
        asr[h] = a_src1[h * 128 + tid];
        adr[h] = a_dst1[h * 128 + tid];
    }
    __syncthreads();
    int n0 = blockIdx.x * 32;
    for (int u = 0; u < 32; u++) {
        int n = n0 + u;
        if (n >= NN) return;
        float xr[9];
#pragma unroll
        for (int k = 0; k < 9; k++) xr[k] = __ldg(&x[n * 9 + k]);
        float p[8];
#pragma unroll
        for (int h = 0; h < 4; h++) {
            float v = 0.f;
#pragma unroll
            for (int k = 0; k < 9; k++) v = fmaf(xr[k], sW[k * 512 + h * 128 + tid], v);
            g_h1[(n * 4 + h) * 128 + tid] = v;
            p[h] = v * asr[h];
            p[4 + h] = v * adr[h];
        }
#pragma unroll
        for (int q = 0; q < 8; q++)
#pragma unroll
            for (int o = 16; o > 0; o >>= 1) p[q] += __shfl_down_sync(0xffffffffu, p[q], o);
        int w = tid >> 5;
        if ((tid & 31) == 0) {
#pragma unroll
            for (int q = 0; q < 8; q++) wsum[w][q] = p[q];
        }
        __syncthreads();
        if (tid < 8) {
            float s = wsum[0][tid] + wsum[1][tid] + wsum[2][tid] + wsum[3][tid];
            if (tid < 4) g_as1[n * 4 + tid] = s;
            else g_ad1[n * 4 + (tid - 4)] = s;
        }
        __syncthreads();
    }
}

// ---------------- layer 1 aggregation; output written as bf16 hi/lo ----------------
__global__ void k_agg1(const float* __restrict__ b1) {
    int n = blockIdx.x, tid = threadIdx.x;
    const float4* as4 = (const float4*)g_as1;
    float4 adv = ((const float4*)g_ad1)[n];
    float4 a0 = as4[n];
    float l0 = lrelu(a0.x + adv.x), l1 = lrelu(a0.y + adv.y);
    float l2 = lrelu(a0.z + adv.z), l3 = lrelu(a0.w + adv.w);
    float m0 = l0, m1 = l1, m2 = l2, m3 = l3;
    int beg = g_rowptr[n], end = g_rowptr[n + 1];
    for (int j = beg; j < end; j++) {
        float4 a = as4[g_col[j]];
        m0 = fmaxf(m0, lrelu(a.x + adv.x));
        m1 = fmaxf(m1, lrelu(a.y + adv.y));
        m2 = fmaxf(m2, lrelu(a.z + adv.z));
        m3 = fmaxf(m3, lrelu(a.w + adv.w));
    }
    float z0 = __expf(l0 - m0), z1 = __expf(l1 - m1);
    float z2 = __expf(l2 - m2), z3 = __expf(l3 - m3);
    const float* hn = g_h1 + n * 512;
    float acc0 = z0 * hn[tid];
    float acc1 = z1 * hn[128 + tid];
    float acc2 = z2 * hn[256 + tid];
    float acc3 = z3 * hn[384 + tid];
    for (int j = beg; j < end; j++) {
        int s = g_col[j];
        float4 a = as4[s];
        float e0 = __expf(lrelu(a.x + adv.x) - m0);
        float e1 = __expf(lrelu(a.y + adv.y) - m1);
        float e2 = __expf(lrelu(a.z + adv.z) - m2);
        float e3 = __expf(lrelu(a.w + adv.w) - m3);
        const float* hs = g_h1 + s * 512;
        acc0 = fmaf(e0, hs[tid], acc0);
        acc1 = fmaf(e1, hs[128 + tid], acc1);
        acc2 = fmaf(e2, hs[256 + tid], acc2);
        acc3 = fmaf(e3, hs[384 + tid], acc3);
        z0 += e0; z1 += e1; z2 += e2; z3 += e3;
    }
    float v[4];
    v[0] = eluf(acc0 / (z0 + 1e-16f) + b1[tid]);
    v[1] = eluf(acc1 / (z1 + 1e-16f) + b1[128 + tid]);
    v[2] = eluf(acc2 / (z2 + 1e-16f) + b1[256 + tid]);
    v[3] = eluf(acc3 / (z3 + 1e-16f) + b1[384 + tid]);
#pragma unroll
    for (int h = 0; h < 4; h++) {
        int idx = n * 512 + h * 128 + tid;
        __nv_bfloat16 hi = __float2bfloat16(v[h]);
        g_a_hi[idx] = hi;
        g_a_lo[idx] = __float2bfloat16(v[h] - __bfloat162float(hi));
    }
}

// ---------------- W2 transpose + bf16 hi/lo split ----------------
__global__ void k_w2prep(const float* __restrict__ W2) {
    int k = blockIdx.x, n = threadIdx.x;   // 512 blocks, 128 threads
    float v = W2[k * 128 + n];
    __nv_bfloat16 hi = __float2bfloat16(v);
    g_w2t_hi[n * 512 + k] = hi;
    g_w2t_lo[n * 512 + k] = __float2bfloat16(v - __bfloat162float(hi));
}

// ---------------- HMMA GEMM2: h2 = o1[100000,512] @ W2[512,128], fused alpha2 ----------------
// CTA tile 128x128, K chunks of 64, bf16 hi/lo split (3 accumulated passes).
// 256 threads = 8 warps arranged 4(M) x 2(N); warp tile 32x64; mma.m16n8k16.
#define SWZC(rowIdx) (((rowIdx) & 7) << 4)

__global__ __launch_bounds__(256, 2) void k_gemm2_mma(const float* __restrict__ a_src2,
                                                      const float* __restrict__ a_dst2) {
    extern __shared__ char smem[];
    // layout: A_hi[16K] A_lo[16K] B_hi[16K] B_lo[16K]
    char* sA_hi = smem;
    char* sA_lo = smem + 16384;
    char* sB_hi = smem + 32768;
    char* sB_lo = smem + 49152;
    uint32_t uA_hi = smem_to_u32(sA_hi);
    uint32_t uA_lo = uA_hi + 16384;
    uint32_t uB_hi = uA_hi + 32768;
    uint32_t uB_lo = uA_hi + 49152;

    int tid = threadIdx.x;
    int lane = tid & 31, wid = tid >> 5;
    int warpM = wid & 3, warpN = wid >> 2;
    int rb = warpM * 32, cb = warpN * 64;
    int m0 = blockIdx.x * 128;

    float acc[2][8][4];
#pragma unroll
    for (int i = 0; i < 2; i++)
#pragma unroll
        for (int j = 0; j < 8; j++)
#pragma unroll
            for (int q = 0; q < 4; q++) acc[i][j][q] = 0.f;

    // global->smem copy mapping: 2 threads per 128B row, 4x uint4 each
    int ldRow = tid >> 1;             // 0..127
    int ldPart = (tid & 1) * 4;       // uint4 index 0 or 4
    int aRow = m0 + ldRow;
    bool aOk = aRow < NN;
    uint32_t ldSwc = SWZC(ldRow);
    uint32_t ldRowOff = ldRow * 128;

    // ldmatrix lane addressing precompute
    int g = lane >> 3;
    // A: rows rb + mf*16 + (g&1)*8 + (lane&7), kbyte (g>>1)*16 (+kk*32)
    int aFr0 = rb + (g & 1) * 8 + (lane & 7);
    uint32_t aKb = (uint32_t)((g >> 1) << 4);
    // B: n rows cb + p*16 + (g>>1)*8 + (lane&7), kbyte (g&1)*16 (+kk*32)
    int bFr0 = cb + (g >> 1) * 8 + (lane & 7);
    uint32_t bKb = (uint32_t)((g & 1) << 4);

    for (int ch = 0; ch < 8; ch++) {
        __syncthreads();
        // ---- load chunk into smem ----
        {
            uint4 zero = make_uint4(0, 0, 0, 0);
            const uint4* pAh = (const uint4*)(g_a_hi + (size_t)aRow * 512 + ch * 64);
            const uint4* pAl = (const uint4*)(g_a_lo + (size_t)aRow * 512 + ch * 64);
            const uint4* pBh = (const uint4*)(g_w2t_hi + (size_t)ldRow * 512 + ch * 64);
            const uint4* pBl = (const uint4*)(g_w2t_lo + (size_t)ldRow * 512 + ch * 64);
#pragma unroll
            for (int i = 0; i < 4; i++) {
                uint32_t kb = (uint32_t)((ldPart + i) << 4);
                uint32_t off = ldRowOff + (kb ^ ldSwc);
                *(uint4*)(sA_hi + off) = aOk ? pAh[ldPart + i] : zero;
                *(uint4*)(sA_lo + off) = aOk ? pAl[ldPart + i] : zero;
                *(uint4*)(sB_hi + off) = pBh[ldPart + i];
                *(uint4*)(sB_lo + off) = pBl[ldPart + i];
            }
        }
        __syncthreads();
        // ---- 4 ksteps of 16 ----
#pragma unroll
        for (int kk = 0; kk < 4; kk++) {
            uint32_t kkb = (uint32_t)(kk << 5);
            uint32_t ah[2][4], al[2][4];
#pragma unroll
            for (int mf = 0; mf < 2; mf++) {
                int r = aFr0 + mf * 16;
                uint32_t off = (uint32_t)(r * 128) + ((kkb + aKb) ^ SWZC(r));
                LDSM_X4(ah[mf][0], ah[mf][1], ah[mf][2], ah[mf][3], uA_hi + off);
                LDSM_X4(al[mf][0], al[mf][1], al[mf][2], al[mf][3], uA_lo + off);
            }
            uint32_t bh[4][4];
#pragma unroll
            for (int p = 0; p < 4; p++) {
                int r = bFr0 + p * 16;
                uint32_t off = (uint32_t)(r * 128) + ((kkb + bKb) ^ SWZC(r));
                LDSM_X4(bh[p][0], bh[p][1], bh[p][2], bh[p][3], uB_hi + off);
            }
#pragma unroll
            for (int mf = 0; mf < 2; mf++)
#pragma unroll
                for (int p = 0; p < 4; p++) {
                    mma16816(acc[mf][2 * p], ah[mf][0], ah[mf][1], ah[mf][2], ah[mf][3],
                             bh[p][0], bh[p][1]);
                    mma16816(acc[mf][2 * p + 1], ah[mf][0], ah[mf][1], ah[mf][2], ah[mf][3],
                             bh[p][2], bh[p][3]);
                    mma16816(acc[mf][2 * p], al[mf][0], al[mf][1], al[mf][2], al[mf][3],
                             bh[p][0], bh[p][1]);
                    mma16816(acc[mf][2 * p + 1], al[mf][0], al[mf][1], al[mf][2], al[mf][3],
                             bh[p][2], bh[p][3]);
                }
            uint32_t bl[4][4];
#pragma unroll
            for (int p = 0; p < 4; p++) {
                int r = bFr0 + p * 16;
                uint32_t off = (uint32_t)(r * 128) + ((kkb + bKb) ^ SWZC(r));
                LDSM_X4(bl[p][0], bl[p][1], bl[p][2], bl[p][3], uB_lo + off);
            }
#pragma unroll
            for (int mf = 0; mf < 2; mf++)
#pragma unroll
                for (int p = 0; p < 4; p++) {
                    mma16816(acc[mf][2 * p], ah[mf][0], ah[mf][1], ah[mf][2], ah[mf][3],
                             bl[p][0], bl[p][1]);
                    mma16816(acc[mf][2 * p + 1], ah[mf][0], ah[mf][1], ah[mf][2], ah[mf][3],
                             bl[p][2], bl[p][3]);
                }
        }
    }
    __syncthreads();

    // ---- epilogue: store h2, fused alpha2 dot products ----
    float* red = (float*)smem;       // [0:128) as2 partials, [128:256) ad2 partials
    if (tid < 256) red[tid] = 0.f;
    __syncthreads();

    float ps[2][2] = {{0.f, 0.f}, {0.f, 0.f}};
    float pd[2][2] = {{0.f, 0.f}, {0.f, 0.f}};
    int rq = lane >> 2;              // 0..7
    int cq = (lane & 3) * 2;
#pragma unroll
    for (int nf = 0; nf < 8; nf++) {
        int c = cb + nf * 8 + cq;
        float2 sv = __ldg((const float2*)(a_src2 + c));
        float2 dv = __ldg((const float2*)(a_dst2 + c));
#pragma unroll
        for (int mf = 0; mf < 2; mf++) {
            float* a = acc[mf][nf];
            ps[mf][0] = fmaf(a[0], sv.x, fmaf(a[1], sv.y, ps[mf][0]));
            ps[mf][1] = fmaf(a[2], sv.x, fmaf(a[3], sv.y, ps[mf][1]));
            pd[mf][0] = fmaf(a[0], dv.x, fmaf(a[1], dv.y, pd[mf][0]));
            pd[mf][1] = fmaf(a[2], dv.x, fmaf(a[3], dv.y, pd[mf][1]));
            int row0 = m0 + rb + mf * 16 + rq;
            if (row0 < NN)
                *(float2*)(g_h2 + (size_t)row0 * 128 + c) = make_float2(a[0], a[1]);
            if (row0 + 8 < NN)
                *(float2*)(g_h2 + (size_t)(row0 + 8) * 128 + c) = make_float2(a[2], a[3]);
        }
    }
#pragma unroll
    for (int mf = 0; mf < 2; mf++)
#pragma unroll
        for (int h = 0; h < 2; h++) {
#pragma unroll
            for (int o = 1; o <= 2; o <<= 1) {
                ps[mf][h] += __shfl_xor_sync(0xffffffffu, ps[mf][h], o);
                pd[mf][h] += __shfl_xor_sync(0xffffffffu, pd[mf][h], o);
            }
        }
    if ((lane & 3) == 0) {
#pragma unroll
        for (int mf = 0; mf < 2; mf++) {
            int lr = rb + mf * 16 + rq;
            atomicAdd(&red[lr], ps[mf][0]);
            atomicAdd(&red[lr + 8], ps[mf][1]);
            atomicAdd(&red[128 + lr], pd[mf][0]);
            atomicAdd(&red[128 + lr + 8], pd[mf][1]);
        }
    }
    __syncthreads();
    if (tid < 128) {
        int row = m0 + tid;
        if (row < NN) {
            g_as2[row] = red[tid];
            g_ad2[row] = red[128 + tid];
        }
    }
}

// ---------------- layer 2 aggregation fused with mean-pool accumulate ----------------
__global__ void k_agg2(const float* __restrict__ b2, const int* __restrict__ batch,
                       float* __restrict__ out) {
    int n = blockIdx.x, tid = threadIdx.x;
    float adn = g_ad2[n];
    float l = lrelu(g_as2[n] + adn);
    float m = l;
    int beg = g_rowptr[n], end = g_rowptr[n + 1];
    for (int j = beg; j < end; j++)
        m = fmaxf(m, lrelu(g_as2[g_col[j]] + adn));
    float z = __expf(l - m);
    float acc = z * g_h2[n * 128 + tid];
    for (int j = beg; j < end; j++) {
        int s = g_col[j];
        float e = __expf(lrelu(g_as2[s] + adn) - m);
        z += e;
        acc = fmaf(e, g_h2[s * 128 + tid], acc);
    }
    float val = eluf(acc / (z + 1e-16f) + b2[tid]);
    atomicAdd(&out[batch[n] * 128 + tid], val);
}

// ---------------- pooling helpers ----------------
__global__ void k_pool_zero(float* __restrict__ out) {
    int i = blockIdx.x * blockDim.x + threadIdx.x;
    if (i < GG * 128) out[i] = 0.f;
    if (i < GG) g_cnt[i] = 0.f;
}

__global__ void k_cnt(const int* __restrict__ batch) {
    int i = blockIdx.x * blockDim.x + threadIdx.x;
    if (i < NN) atomicAdd(&g_cnt[batch[i]], 1.f);
}

__global__ void k_pool_div(float* __restrict__ out) {
    int g = blockIdx.x, tid = threadIdx.x;
    out[g * 128 + tid] /= fmaxf(g_cnt[g], 1.f);
}

// ---------------- launcher ----------------
extern "C" void kernel_launch(void* const* d_in, const int* in_sizes, int n_in,
                              void* d_out, int out_size) {
    const float* x       = (const float*)d_in[0];
    const int*   ei      = (const int*)d_in[1];
    const int*   batch   = (const int*)d_in[2];
    const float* W1      = (const float*)d_in[3];
    const float* a_src1  = (const float*)d_in[4];
    const float* a_dst1  = (const float*)d_in[5];
    const float* b1      = (const float*)d_in[6];
    const float* W2      = (const float*)d_in[7];
    const float* a_src2  = (const float*)d_in[8];
    const float* a_dst2  = (const float*)d_in[9];
    const float* b2      = (const float*)d_in[10];
    float* out = (float*)d_out;

    cudaFuncSetAttribute(k_gemm2_mma, cudaFuncAttributeMaxDynamicSharedMemorySize, 65536);

    k_zero_deg<<<(NN + 255) / 256, 256>>>();
    k_count<<<(EE + 255) / 256, 256>>>(ei);
    k_scan<<<1, 1024>>>();
    k_fill<<<(EE + 255) / 256, 256>>>(ei);

    k_proj1<<<(NN + 31) / 32, 128>>>(x, W1, a_src1, a_dst1);
    k_agg1<<<NN, 128>>>(b1);

    k_w2prep<<<512, 128>>>(W2);
    k_gemm2_mma<<<(NN + 127) / 128, 256, 65536>>>(a_src2, a_dst2);

    k_pool_zero<<<(GG * 128 + 255) / 256, 256>>>(out);
    k_cnt<<<(NN + 255) / 256, 256>>>(batch);
    k_agg2<<<NN, 128>>>(b2, batch, out);
    k_pool_div<<<GG, 128>>>(out);
}

// round 4
// speedup vs baseline: 2.0594x; 1.5618x over previous
#include <cuda_runtime.h>
#include <cuda_bf16.h>
#include <cuda_fp16.h>
#include <cstdint>

#define NN 100000
#define EE 300000
#define GG 4000

// ---------------- scratch (device globals; no allocation) ----------------
__device__ __align__(16) __half g_h1h[NN * 512];          // layer1 features fp16, [n][c][h] (c*4+h)
__device__ __align__(16) float g_as1[NN * 4];
__device__ __align__(16) float g_ad1[NN * 4];
__device__ __align__(16) __nv_bfloat16 g_a_hi[NN * 512];  // layer1 output hi (GEMM A) [n][h*128+c]
__device__ __align__(16) __nv_bfloat16 g_a_lo[NN * 512];  // layer1 output lo
__device__ __align__(16) __nv_bfloat16 g_w2t_hi[128 * 512]; // W2^T hi  [n=128][k=512]
__device__ __align__(16) __nv_bfloat16 g_w2t_lo[128 * 512]; // W2^T lo
__device__ __align__(16) float g_h2[NN * 128];            // layer2 projected features
__device__ float g_as2[NN];
__device__ float g_ad2[NN];
__device__ float g_wa[9][8];                              // folded a_src1/a_dst1 through W1
__device__ int   g_deg[NN];
__device__ int   g_rowptr[NN + 1];
__device__ int   g_cursor[NN];
__device__ int   g_col[EE];
__device__ float g_cnt[GG];

__device__ __forceinline__ float lrelu(float x) { return x > 0.f ? x : 0.2f * x; }
__device__ __forceinline__ float eluf(float x)  { return x > 0.f ? x : (__expf(x) - 1.f); }

__device__ __forceinline__ uint32_t smem_to_u32(const void* p) {
    uint32_t a;
    asm("{ .reg .u64 t; cvta.to.shared.u64 t, %1; cvt.u32.u64 %0, t; }" : "=r"(a) : "l"(p));
    return a;
}

#define LDSM_X4(r0, r1, r2, r3, addr) \
    asm volatile("ldmatrix.sync.aligned.m8n8.x4.shared.b16 {%0,%1,%2,%3}, [%4];" \
        : "=r"(r0), "=r"(r1), "=r"(r2), "=r"(r3) : "r"(addr))

__device__ __forceinline__ void mma16816(float* d, uint32_t a0, uint32_t a1, uint32_t a2,
                                         uint32_t a3, uint32_t b0, uint32_t b1) {
    asm volatile(
        "mma.sync.aligned.m16n8k16.row.col.f32.bf16.bf16.f32 "
        "{%0,%1,%2,%3}, {%4,%5,%6,%7}, {%8,%9}, {%0,%1,%2,%3};"
        : "+f"(d[0]), "+f"(d[1]), "+f"(d[2]), "+f"(d[3])
        : "r"(a0), "r"(a1), "r"(a2), "r"(a3), "r"(b0), "r"(b1));
}

// ---------------- CSR build ----------------
__global__ void k_zero_deg() {
    int i = blockIdx.x * blockDim.x + threadIdx.x;
    if (i < NN) g_deg[i] = 0;
}

__global__ void k_count(const int* __restrict__ ei) {
    int e = blockIdx.x * blockDim.x + threadIdx.x;
    if (e < EE) atomicAdd(&g_deg[ei[EE + e]], 1);
}

__global__ void k_scan() {
    const int CH = 16;
    __shared__ int warp_s[32];
    int tid = threadIdx.x, lane = tid & 31, w = tid >> 5;
    int offset = 0;
    for (int base = 0; base < NN; base += 1024 * CH) {
        int i0 = base + tid * CH;
        int v[CH];
        int tot = 0;
#pragma unroll
        for (int c = 0; c < CH; c++) {
            int idx = i0 + c;
            v[c] = (idx < NN) ? g_deg[idx] : 0;
            tot += v[c];
        }
        int x = tot;
#pragma unroll
        for (int o = 1; o < 32; o <<= 1) {
            int t = __shfl_up_sync(0xffffffffu, x, o);
            if (lane >= o) x += t;
        }
        if (lane == 31) warp_s[w] = x;
        __syncthreads();
        if (w == 0) {
            int y = warp_s[lane];
#pragma unroll
            for (int o = 1; o < 32; o <<= 1) {
                int t = __shfl_up_sync(0xffffffffu, y, o);
                if (lane >= o) y += t;
            }
            warp_s[lane] = y;
        }
        __syncthreads();
        int excl = x - tot + ((w > 0) ? warp_s[w - 1] : 0) + offset;
        int run = excl;
#pragma unroll
        for (int c = 0; c < CH; c++) {
            int idx = i0 + c;
            if (idx < NN) {
                g_cursor[idx] = run;
                run += v[c];
                g_rowptr[idx + 1] = run;
            }
        }
        int total = warp_s[31];
        __syncthreads();
        offset += total;
    }
    if (tid == 0) g_rowptr[0] = 0;
}

__global__ void k_fill(const int* __restrict__ ei) {
    int e = blockIdx.x * blockDim.x + threadIdx.x;
    if (e < EE) {
        int s = ei[e], d = ei[EE + e];
        int p = atomicAdd(&g_cursor[d], 1);
        g_col[p] = s;
    }
}

// ---------------- fold a_src1/a_dst1 through W1: wa[k][q] ----------------
__global__ void k_wa(const float* __restrict__ W1, const float* __restrict__ a_src1,
                     const float* __restrict__ a_dst1) {
    int t = threadIdx.x;
    if (t < 72) {
        int k = t / 8, q = t % 8;
        int h = q & 3;
        const float* a = (q >= 4) ? a_dst1 : a_src1;
        float s = 0.f;
        for (int c = 0; c < 128; c++)
            s = fmaf(W1[k * 512 + h * 128 + c], a[h * 128 + c], s);
        g_wa[k][q] = s;
    }
}

// ---------------- layer 1 projection (sync-free, W in registers) ----------------
// 128 threads/block; warp w covers channels 32w+lane; grid-stride over nodes.
// h1 stored fp16 [n][c][h]; as1/ad1 via precomputed g_wa (warp 0 lanes 0-7).
__global__ __launch_bounds__(128) void k_proj1(const float* __restrict__ x,
                                               const float* __restrict__ W1) {
    int tid = threadIdx.x, lane = tid & 31, w = tid >> 5;
    int c = w * 32 + lane;
    float wreg[9][4];
#pragma unroll
    for (int k = 0; k < 9; k++)
#pragma unroll
        for (int h = 0; h < 4; h++)
            wreg[k][h] = __ldg(&W1[k * 512 + h * 128 + c]);
    float war[9];
    if (w == 0 && lane < 8) {
#pragma unroll
        for (int k = 0; k < 9; k++) war[k] = g_wa[k][lane];
    }
    for (int n = blockIdx.x; n < NN; n += gridDim.x) {
        float xv = (lane < 9) ? __ldg(&x[n * 9 + lane]) : 0.f;
        float xr[9];
#pragma unroll
        for (int k = 0; k < 9; k++) xr[k] = __shfl_sync(0xffffffffu, xv, k);
        float v[4];
#pragma unroll
        for (int h = 0; h < 4; h++) {
            float s = 0.f;
#pragma unroll
            for (int k = 0; k < 9; k++) s = fmaf(xr[k], wreg[k][h], s);
            v[h] = s;
        }
        __half2 p0 = __floats2half2_rn(v[0], v[1]);
        __half2 p1 = __floats2half2_rn(v[2], v[3]);
        uint2 pk;
        pk.x = *(uint32_t*)&p0;
        pk.y = *(uint32_t*)&p1;
        *(uint2*)(g_h1h + (size_t)n * 512 + c * 4) = pk;
        if (w == 0 && lane < 8) {
            float s = 0.f;
#pragma unroll
            for (int k = 0; k < 9; k++) s = fmaf(xr[k], war[k], s);
            if (lane < 4) g_as1[n * 4 + lane] = s;
            else g_ad1[n * 4 + (lane - 4)] = s;
        }
    }
}

// ---------------- layer 1 aggregation: warp per node, fp16 gather ----------------
__global__ __launch_bounds__(256) void k_agg1(const float* __restrict__ b1) {
    int n = blockIdx.x * 8 + (threadIdx.x >> 5);
    if (n >= NN) return;
    int lane = threadIdx.x & 31;
    const float4* as4 = (const float4*)g_as1;
    float4 adv = ((const float4*)g_ad1)[n];
    float4 a0 = as4[n];
    float l0 = lrelu(a0.x + adv.x), l1 = lrelu(a0.y + adv.y);
    float l2 = lrelu(a0.z + adv.z), l3 = lrelu(a0.w + adv.w);
    float m0 = l0, m1 = l1, m2 = l2, m3 = l3;
    int beg = g_rowptr[n], end = g_rowptr[n + 1];
    for (int j = beg; j < end; j++) {
        float4 a = as4[g_col[j]];
        m0 = fmaxf(m0, lrelu(a.x + adv.x));
        m1 = fmaxf(m1, lrelu(a.y + adv.y));
        m2 = fmaxf(m2, lrelu(a.z + adv.z));
        m3 = fmaxf(m3, lrelu(a.w + adv.w));
    }
    float z0 = __expf(l0 - m0), z1 = __expf(l1 - m1);
    float z2 = __expf(l2 - m2), z3 = __expf(l3 - m3);
    // accumulate: acc[j][h], channels c = lane + 32j
    float acc[4][4];
    {
        const uint2* hp = (const uint2*)(g_h1h + (size_t)n * 512);
#pragma unroll
        for (int j = 0; j < 4; j++) {
            uint2 q = hp[lane + 32 * j];
            __half2 h01 = *(__half2*)&q.x;
            __half2 h23 = *(__half2*)&q.y;
            float2 f01 = __half22float2(h01);
            float2 f23 = __half22float2(h23);
            acc[j][0] = z0 * f01.x;
            acc[j][1] = z1 * f01.y;
            acc[j][2] = z2 * f23.x;
            acc[j][3] = z3 * f23.y;
        }
    }
    for (int j = beg; j < end; j++) {
        int s = g_col[j];
        float4 a = as4[s];
        float e0 = __expf(lrelu(a.x + adv.x) - m0);
        float e1 = __expf(lrelu(a.y + adv.y) - m1);
        float e2 = __expf(lrelu(a.z + adv.z) - m2);
        float e3 = __expf(lrelu(a.w + adv.w) - m3);
        const uint2* hp = (const uint2*)(g_h1h + (size_t)s * 512);
#pragma unroll
        for (int jj = 0; jj < 4; jj++) {
            uint2 q = hp[lane + 32 * jj];
            __half2 h01 = *(__half2*)&q.x;
            __half2 h23 = *(__half2*)&q.y;
            float2 f01 = __half22float2(h01);
            float2 f23 = __half22float2(h23);
            acc[jj][0] = fmaf(e0, f01.x, acc[jj][0]);
            acc[jj][1] = fmaf(e1, f01.y, acc[jj][1]);
            acc[jj][2] = fmaf(e2, f23.x, acc[jj][2]);
            acc[jj][3] = fmaf(e3, f23.y, acc[jj][3]);
        }
        z0 += e0; z1 += e1; z2 += e2; z3 += e3;
    }
    float iz0 = 1.f / (z0 + 1e-16f), iz1 = 1.f / (z1 + 1e-16f);
    float iz2 = 1.f / (z2 + 1e-16f), iz3 = 1.f / (z3 + 1e-16f);
#pragma unroll
    for (int j = 0; j < 4; j++) {
        int c = lane + 32 * j;
        float v0 = eluf(acc[j][0] * iz0 + __ldg(&b1[c]));
        float v1 = eluf(acc[j][1] * iz1 + __ldg(&b1[128 + c]));
        float v2 = eluf(acc[j][2] * iz2 + __ldg(&b1[256 + c]));
        float v3 = eluf(acc[j][3] * iz3 + __ldg(&b1[384 + c]));
        float vv[4] = {v0, v1, v2, v3};
#pragma unroll
        for (int h = 0; h < 4; h++) {
            size_t idx = (size_t)n * 512 + h * 128 + c;
            __nv_bfloat16 hi = __float2bfloat16(vv[h]);
            g_a_hi[idx] = hi;
            g_a_lo[idx] = __float2bfloat16(vv[h] - __bfloat162float(hi));
        }
    }
}

// ---------------- W2 transpose + bf16 hi/lo split ----------------
__global__ void k_w2prep(const float* __restrict__ W2) {
    int k = blockIdx.x, n = threadIdx.x;
    float v = W2[k * 128 + n];
    __nv_bfloat16 hi = __float2bfloat16(v);
    g_w2t_hi[n * 512 + k] = hi;
    g_w2t_lo[n * 512 + k] = __float2bfloat16(v - __bfloat162float(hi));
}

// ---------------- HMMA GEMM2 (unchanged from round 3) ----------------
#define SWZC(rowIdx) (((rowIdx) & 7) << 4)

__global__ __launch_bounds__(256, 2) void k_gemm2_mma(const float* __restrict__ a_src2,
                                                      const float* __restrict__ a_dst2) {
    extern __shared__ char smem[];
    char* sA_hi = smem;
    char* sA_lo = smem + 16384;
    char* sB_hi = smem + 32768;
    char* sB_lo = smem + 49152;
    uint32_t uA_hi = smem_to_u32(sA_hi);
    uint32_t uA_lo = uA_hi + 16384;
    uint32_t uB_hi = uA_hi + 32768;
    uint32_t uB_lo = uA_hi + 49152;

    int tid = threadIdx.x;
    int lane = tid & 31, wid = tid >> 5;
    int warpM = wid & 3, warpN = wid >> 2;
    int rb = warpM * 32, cb = warpN * 64;
    int m0 = blockIdx.x * 128;

    float acc[2][8][4];
#pragma unroll
    for (int i = 0; i < 2; i++)
#pragma unroll
        for (int j = 0; j < 8; j++)
#pragma unroll
            for (int q = 0; q < 4; q++) acc[i][j][q] = 0.f;

    int ldRow = tid >> 1;
    int ldPart = (tid & 1) * 4;
    int aRow = m0 + ldRow;
    bool aOk = aRow < NN;
    uint32_t ldSwc = SWZC(ldRow);
    uint32_t ldRowOff = ldRow * 128;

    int g = lane >> 3;
    int aFr0 = rb + (g & 1) * 8 + (lane & 7);
    uint32_t aKb = (uint32_t)((g >> 1) << 4);
    int bFr0 = cb + (g >> 1) * 8 + (lane & 7);
    uint32_t bKb = (uint32_t)((g & 1) << 4);

    for (int ch = 0; ch < 8; ch++) {
        __syncthreads();
        {
            uint4 zero = make_uint4(0, 0, 0, 0);
            const uint4* pAh = (const uint4*)(g_a_hi + (size_t)aRow * 512 + ch * 64);
            const uint4* pAl = (const uint4*)(g_a_lo + (size_t)aRow * 512 + ch * 64);
            const uint4* pBh = (const uint4*)(g_w2t_hi + (size_t)ldRow * 512 + ch * 64);
            const uint4* pBl = (const uint4*)(g_w2t_lo + (size_t)ldRow * 512 + ch * 64);
#pragma unroll
            for (int i = 0; i < 4; i++) {
                uint32_t kb = (uint32_t)((ldPart + i) << 4);
                uint32_t off = ldRowOff + (kb ^ ldSwc);
                *(uint4*)(sA_hi + off) = aOk ? pAh[ldPart + i] : zero;
                *(uint4*)(sA_lo + off) = aOk ? pAl[ldPart + i] : zero;
                *(uint4*)(sB_hi + off) = pBh[ldPart + i];
                *(uint4*)(sB_lo + off) = pBl[ldPart + i];
            }
        }
        __syncthreads();
#pragma unroll
        for (int kk = 0; kk < 4; kk++) {
            uint32_t kkb = (uint32_t)(kk << 5);
            uint32_t ah[2][4], al[2][4];
#pragma unroll
            for (int mf = 0; mf < 2; mf++) {
                int r = aFr0 + mf * 16;
                uint32_t off = (uint32_t)(r * 128) + ((kkb + aKb) ^ SWZC(r));
                LDSM_X4(ah[mf][0], ah[mf][1], ah[mf][2], ah[mf][3], uA_hi + off);
                LDSM_X4(al[mf][0], al[mf][1], al[mf][2], al[mf][3], uA_lo + off);
            }
            uint32_t bh[4][4];
#pragma unroll
            for (int p = 0; p < 4; p++) {
                int r = bFr0 + p * 16;
                uint32_t off = (uint32_t)(r * 128) + ((kkb + bKb) ^ SWZC(r));
                LDSM_X4(bh[p][0], bh[p][1], bh[p][2], bh[p][3], uB_hi + off);
            }
#pragma unroll
            for (int mf = 0; mf < 2; mf++)
#pragma unroll
                for (int p = 0; p < 4; p++) {
                    mma16816(acc[mf][2 * p], ah[mf][0], ah[mf][1], ah[mf][2], ah[mf][3],
                             bh[p][0], bh[p][1]);
                    mma16816(acc[mf][2 * p + 1], ah[mf][0], ah[mf][1], ah[mf][2], ah[mf][3],
                             bh[p][2], bh[p][3]);
                    mma16816(acc[mf][2 * p], al[mf][0], al[mf][1], al[mf][2], al[mf][3],
                             bh[p][0], bh[p][1]);
                    mma16816(acc[mf][2 * p + 1], al[mf][0], al[mf][1], al[mf][2], al[mf][3],
                             bh[p][2], bh[p][3]);
                }
            uint32_t bl[4][4];
#pragma unroll
            for (int p = 0; p < 4; p++) {
                int r = bFr0 + p * 16;
                uint32_t off = (uint32_t)(r * 128) + ((kkb + bKb) ^ SWZC(r));
                LDSM_X4(bl[p][0], bl[p][1], bl[p][2], bl[p][3], uB_lo + off);
            }
#pragma unroll
            for (int mf = 0; mf < 2; mf++)
#pragma unroll
                for (int p = 0; p < 4; p++) {
                    mma16816(acc[mf][2 * p], ah[mf][0], ah[mf][1], ah[mf][2], ah[mf][3],
                             bl[p][0], bl[p][1]);
                    mma16816(acc[mf][2 * p + 1], ah[mf][0], ah[mf][1], ah[mf][2], ah[mf][3],
                             bl[p][2], bl[p][3]);
                }
        }
    }
    __syncthreads();

    float* red = (float*)smem;
    if (tid < 256) red[tid] = 0.f;
    __syncthreads();

    float ps[2][2] = {{0.f, 0.f}, {0.f, 0.f}};
    float pd[2][2] = {{0.f, 0.f}, {0.f, 0.f}};
    int rq = lane >> 2;
    int cq = (lane & 3) * 2;
#pragma unroll
    for (int nf = 0; nf < 8; nf++) {
        int c = cb + nf * 8 + cq;
        float2 sv = __ldg((const float2*)(a_src2 + c));
        float2 dv = __ldg((const float2*)(a_dst2 + c));
#pragma unroll
        for (int mf = 0; mf < 2; mf++) {
            float* a = acc[mf][nf];
            ps[mf][0] = fmaf(a[0], sv.x, fmaf(a[1], sv.y, ps[mf][0]));
            ps[mf][1] = fmaf(a[2], sv.x, fmaf(a[3], sv.y, ps[mf][1]));
            pd[mf][0] = fmaf(a[0], dv.x, fmaf(a[1], dv.y, pd[mf][0]));
            pd[mf][1] = fmaf(a[2], dv.x, fmaf(a[3], dv.y, pd[mf][1]));
            int row0 = m0 + rb + mf * 16 + rq;
            if (row0 < NN)
                *(float2*)(g_h2 + (size_t)row0 * 128 + c) = make_float2(a[0], a[1]);
            if (row0 + 8 < NN)
                *(float2*)(g_h2 + (size_t)(row0 + 8) * 128 + c) = make_float2(a[2], a[3]);
        }
    }
#pragma unroll
    for (int mf = 0; mf < 2; mf++)
#pragma unroll
        for (int h = 0; h < 2; h++) {
#pragma unroll
            for (int o = 1; o <= 2; o <<= 1) {
                ps[mf][h] += __shfl_xor_sync(0xffffffffu, ps[mf][h], o);
                pd[mf][h] += __shfl_xor_sync(0xffffffffu, pd[mf][h], o);
            }
        }
    if ((lane & 3) == 0) {
#pragma unroll
        for (int mf = 0; mf < 2; mf++) {
            int lr = rb + mf * 16 + rq;
            atomicAdd(&red[lr], ps[mf][0]);
            atomicAdd(&red[lr + 8], ps[mf][1]);
            atomicAdd(&red[128 + lr], pd[mf][0]);
            atomicAdd(&red[128 + lr + 8], pd[mf][1]);
        }
    }
    __syncthreads();
    if (tid < 128) {
        int row = m0 + tid;
        if (row < NN) {
            g_as2[row] = red[tid];
            g_ad2[row] = red[128 + tid];
        }
    }
}

// ---------------- layer 2 aggregation (warp per node) + pooled atomicAdd ----------------
__global__ __launch_bounds__(256) void k_agg2(const float* __restrict__ b2,
                                              const int* __restrict__ batch,
                                              float* __restrict__ out) {
    int n = blockIdx.x * 8 + (threadIdx.x >> 5);
    if (n >= NN) return;
    int lane = threadIdx.x & 31;
    float adn = g_ad2[n];
    float l = lrelu(g_as2[n] + adn);
    float m = l;
    int beg = g_rowptr[n], end = g_rowptr[n + 1];
    for (int j = beg; j < end; j++)
        m = fmaxf(m, lrelu(g_as2[g_col[j]] + adn));
    float z = __expf(l - m);
    float4 hv = *(const float4*)(g_h2 + (size_t)n * 128 + lane * 4);
    float a0 = z * hv.x, a1 = z * hv.y, a2 = z * hv.z, a3 = z * hv.w;
    for (int j = beg; j < end; j++) {
        int s = g_col[j];
        float e = __expf(lrelu(g_as2[s] + adn) - m);
        float4 h = *(const float4*)(g_h2 + (size_t)s * 128 + lane * 4);
        a0 = fmaf(e, h.x, a0);
        a1 = fmaf(e, h.y, a1);
        a2 = fmaf(e, h.z, a2);
        a3 = fmaf(e, h.w, a3);
        z += e;
    }
    float iz = 1.f / (z + 1e-16f);
    float4 bv = *(const float4*)(b2 + lane * 4);
    int g = batch[n];
    float* o = out + (size_t)g * 128 + lane * 4;
    atomicAdd(o + 0, eluf(a0 * iz + bv.x));
    atomicAdd(o + 1, eluf(a1 * iz + bv.y));
    atomicAdd(o + 2, eluf(a2 * iz + bv.z));
    atomicAdd(o + 3, eluf(a3 * iz + bv.w));
}

// ---------------- pooling helpers ----------------
__global__ void k_pool_zero(float* __restrict__ out) {
    int i = blockIdx.x * blockDim.x + threadIdx.x;
    if (i < GG * 128) out[i] = 0.f;
    if (i < GG) g_cnt[i] = 0.f;
}

__global__ void k_cnt(const int* __restrict__ batch) {
    int i = blockIdx.x * blockDim.x + threadIdx.x;
    if (i < NN) atomicAdd(&g_cnt[batch[i]], 1.f);
}

__global__ void k_pool_div(float* __restrict__ out) {
    int g = blockIdx.x, tid = threadIdx.x;
    out[g * 128 + tid] /= fmaxf(g_cnt[g], 1.f);
}

// ---------------- launcher ----------------
extern "C" void kernel_launch(void* const* d_in, const int* in_sizes, int n_in,
                              void* d_out, int out_size) {
    const float* x       = (const float*)d_in[0];
    const int*   ei      = (const int*)d_in[1];
    const int*   batch   = (const int*)d_in[2];
    const float* W1      = (const float*)d_in[3];
    const float* a_src1  = (const float*)d_in[4];
    const float* a_dst1  = (const float*)d_in[5];
    const float* b1      = (const float*)d_in[6];
    const float* W2      = (const float*)d_in[7];
    const float* a_src2  = (const float*)d_in[8];
    const float* a_dst2  = (const float*)d_in[9];
    const float* b2      = (const float*)d_in[10];
    float* out = (float*)d_out;

    cudaFuncSetAttribute(k_gemm2_mma, cudaFuncAttributeMaxDynamicSharedMemorySize, 65536);

    k_zero_deg<<<(NN + 255) / 256, 256>>>();
    k_count<<<(EE + 255) / 256, 256>>>(ei);
    k_scan<<<1, 1024>>>();
    k_fill<<<(EE + 255) / 256, 256>>>(ei);

    k_wa<<<1, 128>>>(W1, a_src1, a_dst1);
    k_proj1<<<4096, 128>>>(x, W1);
    k_agg1<<<(NN + 7) / 8, 256>>>(b1);

    k_w2prep<<<512, 128>>>(W2);
    k_gemm2_mma<<<(NN + 127) / 128, 256, 65536>>>(a_src2, a_dst2);

    k_pool_zero<<<(GG * 128 + 255) / 256, 256>>>(out);
    k_cnt<<<(NN + 255) / 256, 256>>>(batch);
    k_agg2<<<(NN + 7) / 8, 256>>>(b2, batch, out);
    k_pool_div<<<GG, 128>>>(out);
}

// round 5
// speedup vs baseline: 2.9044x; 1.4103x over previous
#include <cuda_runtime.h>
#include <cuda_bf16.h>
#include <cuda_fp16.h>
#include <cstdint>

#define NN 100000
#define EE 300000
#define GG 4000
#define CAP 32

// ---------------- scratch (device globals; no allocation) ----------------
__device__ __align__(16) __half g_h1h[NN * 512];          // layer1 features fp16, [n][c][h] (c*4+h)
__device__ __align__(16) float g_as1[NN * 4];
__device__ __align__(16) float g_ad1[NN * 4];
__device__ __align__(16) __half g_o1h[NN * 512];          // layer1 output fp16 (GEMM A) [n][h*128+c]
__device__ __align__(16) __half g_w2t_hi[128 * 512];      // W2^T hi fp16 [n=128][k=512]
__device__ __align__(16) __half g_w2t_lo[128 * 512];      // W2^T lo fp16
__device__ __align__(16) __half g_h2h[NN * 128];          // layer2 projected features fp16
__device__ float g_as2[NN];
__device__ float g_ad2[NN];
__device__ float g_wa[9][8];                              // folded a_src1/a_dst1 through W1
__device__ int   g_deg[NN];
__device__ int   g_col[NN * CAP];
__device__ float g_cnt[GG];

__device__ __forceinline__ float lrelu(float x) { return x > 0.f ? x : 0.2f * x; }
__device__ __forceinline__ float eluf(float x)  { return x > 0.f ? x : (__expf(x) - 1.f); }

__device__ __forceinline__ uint32_t smem_to_u32(const void* p) {
    uint32_t a;
    asm("{ .reg .u64 t; cvta.to.shared.u64 t, %1; cvt.u32.u64 %0, t; }" : "=r"(a) : "l"(p));
    return a;
}

#define LDSM_X4(r0, r1, r2, r3, addr) \
    asm volatile("ldmatrix.sync.aligned.m8n8.x4.shared.b16 {%0,%1,%2,%3}, [%4];" \
        : "=r"(r0), "=r"(r1), "=r"(r2), "=r"(r3) : "r"(addr))

__device__ __forceinline__ void mma16816h(float* d, uint32_t a0, uint32_t a1, uint32_t a2,
                                          uint32_t a3, uint32_t b0, uint32_t b1) {
    asm volatile(
        "mma.sync.aligned.m16n8k16.row.col.f32.f16.f16.f32 "
        "{%0,%1,%2,%3}, {%4,%5,%6,%7}, {%8,%9}, {%0,%1,%2,%3};"
        : "+f"(d[0]), "+f"(d[1]), "+f"(d[2]), "+f"(d[3])
        : "r"(a0), "r"(a1), "r"(a2), "r"(a3), "r"(b0), "r"(b1));
}

// ---------------- init: zero out / deg / cnt in one pass ----------------
__global__ void k_init(float* __restrict__ out) {
    int i = blockIdx.x * blockDim.x + threadIdx.x;
    if (i < GG * 128) out[i] = 0.f;
    if (i < NN) g_deg[i] = 0;
    if (i < GG) g_cnt[i] = 0.f;
}

// ---------------- adjacency fill (slot array, no scan) ----------------
__global__ void k_fill(const int* __restrict__ ei) {
    int e = blockIdx.x * blockDim.x + threadIdx.x;
    if (e < EE) {
        int s = ei[e], d = ei[EE + e];
        int p = atomicAdd(&g_deg[d], 1);
        if (p < CAP) g_col[d * CAP + p] = s;
    }
}

__global__ void k_cnt(const int* __restrict__ batch) {
    int i = blockIdx.x * blockDim.x + threadIdx.x;
    if (i < NN) atomicAdd(&g_cnt[batch[i]], 1.f);
}

// ---------------- fold a_src1/a_dst1 through W1: wa[k][q] ----------------
__global__ void k_wa(const float* __restrict__ W1, const float* __restrict__ a_src1,
                     const float* __restrict__ a_dst1) {
    int t = threadIdx.x;
    if (t < 72) {
        int k = t / 8, q = t % 8;
        int h = q & 3;
        const float* a = (q >= 4) ? a_dst1 : a_src1;
        float s = 0.f;
        for (int c = 0; c < 128; c++)
            s = fmaf(W1[k * 512 + h * 128 + c], a[h * 128 + c], s);
        g_wa[k][q] = s;
    }
}

// ---------------- layer 1 projection (sync-free, W in registers) ----------------
__global__ __launch_bounds__(128) void k_proj1(const float* __restrict__ x,
                                               const float* __restrict__ W1) {
    int tid = threadIdx.x, lane = tid & 31, w = tid >> 5;
    int c = w * 32 + lane;
    float wreg[9][4];
#pragma unroll
    for (int k = 0; k < 9; k++)
#pragma unroll
        for (int h = 0; h < 4; h++)
            wreg[k][h] = __ldg(&W1[k * 512 + h * 128 + c]);
    float war[9];
    if (w == 0 && lane < 8) {
#pragma unroll
        for (int k = 0; k < 9; k++) war[k] = g_wa[k][lane];
    }
    for (int n = blockIdx.x; n < NN; n += gridDim.x) {
        float xv = (lane < 9) ? __ldg(&x[n * 9 + lane]) : 0.f;
        float xr[9];
#pragma unroll
        for (int k = 0; k < 9; k++) xr[k] = __shfl_sync(0xffffffffu, xv, k);
        float v[4];
#pragma unroll
        for (int h = 0; h < 4; h++) {
            float s = 0.f;
#pragma unroll
            for (int k = 0; k < 9; k++) s = fmaf(xr[k], wreg[k][h], s);
            v[h] = s;
        }
        __half2 p0 = __floats2half2_rn(v[0], v[1]);
        __half2 p1 = __floats2half2_rn(v[2], v[3]);
        uint2 pk;
        pk.x = *(uint32_t*)&p0;
        pk.y = *(uint32_t*)&p1;
        *(uint2*)(g_h1h + (size_t)n * 512 + c * 4) = pk;
        if (w == 0 && lane < 8) {
            float s = 0.f;
#pragma unroll
            for (int k = 0; k < 9; k++) s = fmaf(xr[k], war[k], s);
            if (lane < 4) g_as1[n * 4 + lane] = s;
            else g_ad1[n * 4 + (lane - 4)] = s;
        }
    }
}

// ---------------- layer 1 aggregation: warp per node, fp16 gather, fp16 output ----------------
__global__ __launch_bounds__(256) void k_agg1(const float* __restrict__ b1) {
    int n = blockIdx.x * 8 + (threadIdx.x >> 5);
    if (n >= NN) return;
    int lane = threadIdx.x & 31;
    const float4* as4 = (const float4*)g_as1;
    float4 adv = ((const float4*)g_ad1)[n];
    float4 a0 = as4[n];
    float l0 = lrelu(a0.x + adv.x), l1 = lrelu(a0.y + adv.y);
    float l2 = lrelu(a0.z + adv.z), l3 = lrelu(a0.w + adv.w);
    float m0 = l0, m1 = l1, m2 = l2, m3 = l3;
    int deg = min(g_deg[n], CAP);
    const int* col = g_col + n * CAP;
    for (int j = 0; j < deg; j++) {
        float4 a = as4[col[j]];
        m0 = fmaxf(m0, lrelu(a.x + adv.x));
        m1 = fmaxf(m1, lrelu(a.y + adv.y));
        m2 = fmaxf(m2, lrelu(a.z + adv.z));
        m3 = fmaxf(m3, lrelu(a.w + adv.w));
    }
    float z0 = __expf(l0 - m0), z1 = __expf(l1 - m1);
    float z2 = __expf(l2 - m2), z3 = __expf(l3 - m3);
    float acc[4][4];
    {
        const uint2* hp = (const uint2*)(g_h1h + (size_t)n * 512);
#pragma unroll
        for (int j = 0; j < 4; j++) {
            uint2 q = hp[lane + 32 * j];
            float2 f01 = __half22float2(*(__half2*)&q.x);
            float2 f23 = __half22float2(*(__half2*)&q.y);
            acc[j][0] = z0 * f01.x;
            acc[j][1] = z1 * f01.y;
            acc[j][2] = z2 * f23.x;
            acc[j][3] = z3 * f23.y;
        }
    }
    for (int j = 0; j < deg; j++) {
        int s = col[j];
        float4 a = as4[s];
        float e0 = __expf(lrelu(a.x + adv.x) - m0);
        float e1 = __expf(lrelu(a.y + adv.y) - m1);
        float e2 = __expf(lrelu(a.z + adv.z) - m2);
        float e3 = __expf(lrelu(a.w + adv.w) - m3);
        const uint2* hp = (const uint2*)(g_h1h + (size_t)s * 512);
#pragma unroll
        for (int jj = 0; jj < 4; jj++) {
            uint2 q = hp[lane + 32 * jj];
            float2 f01 = __half22float2(*(__half2*)&q.x);
            float2 f23 = __half22float2(*(__half2*)&q.y);
            acc[jj][0] = fmaf(e0, f01.x, acc[jj][0]);
            acc[jj][1] = fmaf(e1, f01.y, acc[jj][1]);
            acc[jj][2] = fmaf(e2, f23.x, acc[jj][2]);
            acc[jj][3] = fmaf(e3, f23.y, acc[jj][3]);
        }
        z0 += e0; z1 += e1; z2 += e2; z3 += e3;
    }
    float iz0 = 1.f / (z0 + 1e-16f), iz1 = 1.f / (z1 + 1e-16f);
    float iz2 = 1.f / (z2 + 1e-16f), iz3 = 1.f / (z3 + 1e-16f);
#pragma unroll
    for (int j = 0; j < 4; j++) {
        int c = lane + 32 * j;
        float vv[4];
        vv[0] = eluf(acc[j][0] * iz0 + __ldg(&b1[c]));
        vv[1] = eluf(acc[j][1] * iz1 + __ldg(&b1[128 + c]));
        vv[2] = eluf(acc[j][2] * iz2 + __ldg(&b1[256 + c]));
        vv[3] = eluf(acc[j][3] * iz3 + __ldg(&b1[384 + c]));
#pragma unroll
        for (int h = 0; h < 4; h++)
            g_o1h[(size_t)n * 512 + h * 128 + c] = __float2half(vv[h]);
    }
}

// ---------------- W2 transpose + fp16 hi/lo split ----------------
__global__ void k_w2prep(const float* __restrict__ W2) {
    int k = blockIdx.x, n = threadIdx.x;
    float v = W2[k * 128 + n];
    __half hi = __float2half(v);
    g_w2t_hi[n * 512 + k] = hi;
    g_w2t_lo[n * 512 + k] = __float2half(v - __half2float(hi));
}

// ---------------- HMMA GEMM2 (fp16 A single, W hi/lo), fused alpha2, fp16 h2 ----------------
#define SWZC(rowIdx) (((rowIdx) & 7) << 4)

__global__ __launch_bounds__(256, 2) void k_gemm2_mma(const float* __restrict__ a_src2,
                                                      const float* __restrict__ a_dst2) {
    extern __shared__ char smem[];
    char* sA = smem;                  // 16 KB
    char* sB_hi = smem + 16384;       // 16 KB
    char* sB_lo = smem + 32768;       // 16 KB
    uint32_t uA = smem_to_u32(sA);
    uint32_t uB_hi = uA + 16384;
    uint32_t uB_lo = uA + 32768;

    int tid = threadIdx.x;
    int lane = tid & 31, wid = tid >> 5;
    int warpM = wid & 3, warpN = wid >> 2;
    int rb = warpM * 32, cb = warpN * 64;
    int m0 = blockIdx.x * 128;

    float acc[2][8][4];
#pragma unroll
    for (int i = 0; i < 2; i++)
#pragma unroll
        for (int j = 0; j < 8; j++)
#pragma unroll
            for (int q = 0; q < 4; q++) acc[i][j][q] = 0.f;

    int ldRow = tid >> 1;
    int ldPart = (tid & 1) * 4;
    int aRow = m0 + ldRow;
    bool aOk = aRow < NN;
    uint32_t ldSwc = SWZC(ldRow);
    uint32_t ldRowOff = ldRow * 128;

    int g = lane >> 3;
    int aFr0 = rb + (g & 1) * 8 + (lane & 7);
    uint32_t aKb = (uint32_t)((g >> 1) << 4);
    int bFr0 = cb + (g >> 1) * 8 + (lane & 7);
    uint32_t bKb = (uint32_t)((g & 1) << 4);

    for (int ch = 0; ch < 8; ch++) {
        __syncthreads();
        {
            uint4 zero = make_uint4(0, 0, 0, 0);
            const uint4* pA = (const uint4*)(g_o1h + (size_t)aRow * 512 + ch * 64);
            const uint4* pBh = (const uint4*)(g_w2t_hi + (size_t)ldRow * 512 + ch * 64);
            const uint4* pBl = (const uint4*)(g_w2t_lo + (size_t)ldRow * 512 + ch * 64);
#pragma unroll
            for (int i = 0; i < 4; i++) {
                uint32_t kb = (uint32_t)((ldPart + i) << 4);
                uint32_t off = ldRowOff + (kb ^ ldSwc);
                *(uint4*)(sA + off) = aOk ? pA[ldPart + i] : zero;
                *(uint4*)(sB_hi + off) = pBh[ldPart + i];
                *(uint4*)(sB_lo + off) = pBl[ldPart + i];
            }
        }
        __syncthreads();
#pragma unroll
        for (int kk = 0; kk < 4; kk++) {
            uint32_t kkb = (uint32_t)(kk << 5);
            uint32_t ah[2][4];
#pragma unroll
            for (int mf = 0; mf < 2; mf++) {
                int r = aFr0 + mf * 16;
                uint32_t off = (uint32_t)(r * 128) + ((kkb + aKb) ^ SWZC(r));
                LDSM_X4(ah[mf][0], ah[mf][1], ah[mf][2], ah[mf][3], uA + off);
            }
            uint32_t bh[4][4];
#pragma unroll
            for (int p = 0; p < 4; p++) {
                int r = bFr0 + p * 16;
                uint32_t off = (uint32_t)(r * 128) + ((kkb + bKb) ^ SWZC(r));
                LDSM_X4(bh[p][0], bh[p][1], bh[p][2], bh[p][3], uB_hi + off);
            }
#pragma unroll
            for (int mf = 0; mf < 2; mf++)
#pragma unroll
                for (int p = 0; p < 4; p++) {
                    mma16816h(acc[mf][2 * p], ah[mf][0], ah[mf][1], ah[mf][2], ah[mf][3],
                              bh[p][0], bh[p][1]);
                    mma16816h(acc[mf][2 * p + 1], ah[mf][0], ah[mf][1], ah[mf][2], ah[mf][3],
                              bh[p][2], bh[p][3]);
                }
            uint32_t bl[4][4];
#pragma unroll
            for (int p = 0; p < 4; p++) {
                int r = bFr0 + p * 16;
                uint32_t off = (uint32_t)(r * 128) + ((kkb + bKb) ^ SWZC(r));
                LDSM_X4(bl[p][0], bl[p][1], bl[p][2], bl[p][3], uB_lo + off);
            }
#pragma unroll
            for (int mf = 0; mf < 2; mf++)
#pragma unroll
                for (int p = 0; p < 4; p++) {
                    mma16816h(acc[mf][2 * p], ah[mf][0], ah[mf][1], ah[mf][2], ah[mf][3],
                              bl[p][0], bl[p][1]);
                    mma16816h(acc[mf][2 * p + 1], ah[mf][0], ah[mf][1], ah[mf][2], ah[mf][3],
                              bl[p][2], bl[p][3]);
                }
        }
    }
    __syncthreads();

    float* red = (float*)smem;
    if (tid < 256) red[tid] = 0.f;
    __syncthreads();

    float ps[2][2] = {{0.f, 0.f}, {0.f, 0.f}};
    float pd[2][2] = {{0.f, 0.f}, {0.f, 0.f}};
    int rq = lane >> 2;
    int cq = (lane & 3) * 2;
#pragma unroll
    for (int nf = 0; nf < 8; nf++) {
        int c = cb + nf * 8 + cq;
        float2 sv = __ldg((const float2*)(a_src2 + c));
        float2 dv = __ldg((const float2*)(a_dst2 + c));
#pragma unroll
        for (int mf = 0; mf < 2; mf++) {
            float* a = acc[mf][nf];
            ps[mf][0] = fmaf(a[0], sv.x, fmaf(a[1], sv.y, ps[mf][0]));
            ps[mf][1] = fmaf(a[2], sv.x, fmaf(a[3], sv.y, ps[mf][1]));
            pd[mf][0] = fmaf(a[0], dv.x, fmaf(a[1], dv.y, pd[mf][0]));
            pd[mf][1] = fmaf(a[2], dv.x, fmaf(a[3], dv.y, pd[mf][1]));
            int row0 = m0 + rb + mf * 16 + rq;
            if (row0 < NN) {
                __half2 hh = __floats2half2_rn(a[0], a[1]);
                *(__half2*)(g_h2h + (size_t)row0 * 128 + c) = hh;
            }
            if (row0 + 8 < NN) {
                __half2 hh = __floats2half2_rn(a[2], a[3]);
                *(__half2*)(g_h2h + (size_t)(row0 + 8) * 128 + c) = hh;
            }
        }
    }
#pragma unroll
    for (int mf = 0; mf < 2; mf++)
#pragma unroll
        for (int h = 0; h < 2; h++) {
#pragma unroll
            for (int o = 1; o <= 2; o <<= 1) {
                ps[mf][h] += __shfl_xor_sync(0xffffffffu, ps[mf][h], o);
                pd[mf][h] += __shfl_xor_sync(0xffffffffu, pd[mf][h], o);
            }
        }
    if ((lane & 3) == 0) {
#pragma unroll
        for (int mf = 0; mf < 2; mf++) {
            int lr = rb + mf * 16 + rq;
            atomicAdd(&red[lr], ps[mf][0]);
            atomicAdd(&red[lr + 8], ps[mf][1]);
            atomicAdd(&red[128 + lr], pd[mf][0]);
            atomicAdd(&red[128 + lr + 8], pd[mf][1]);
        }
    }
    __syncthreads();
    if (tid < 128) {
        int row = m0 + tid;
        if (row < NN) {
            g_as2[row] = red[tid];
            g_ad2[row] = red[128 + tid];
        }
    }
}

// ---------------- layer 2 aggregation (warp per node) + pooled atomicAdd ----------------
__global__ __launch_bounds__(256) void k_agg2(const float* __restrict__ b2,
                                              const int* __restrict__ batch,
                                              float* __restrict__ out) {
    int n = blockIdx.x * 8 + (threadIdx.x >> 5);
    if (n >= NN) return;
    int lane = threadIdx.x & 31;
    float adn = g_ad2[n];
    float l = lrelu(g_as2[n] + adn);
    float m = l;
    int deg = min(g_deg[n], CAP);
    const int* col = g_col + n * CAP;
    for (int j = 0; j < deg; j++)
        m = fmaxf(m, lrelu(g_as2[col[j]] + adn));
    float z = __expf(l - m);
    float a0, a1, a2, a3;
    {
        uint2 q = *(const uint2*)(g_h2h + (size_t)n * 128 + lane * 4);
        float2 f01 = __half22float2(*(__half2*)&q.x);
        float2 f23 = __half22float2(*(__half2*)&q.y);
        a0 = z * f01.x; a1 = z * f01.y; a2 = z * f23.x; a3 = z * f23.y;
    }
    for (int j = 0; j < deg; j++) {
        int s = col[j];
        float e = __expf(lrelu(g_as2[s] + adn) - m);
        uint2 q = *(const uint2*)(g_h2h + (size_t)s * 128 + lane * 4);
        float2 f01 = __half22float2(*(__half2*)&q.x);
        float2 f23 = __half22float2(*(__half2*)&q.y);
        a0 = fmaf(e, f01.x, a0);
        a1 = fmaf(e, f01.y, a1);
        a2 = fmaf(e, f23.x, a2);
        a3 = fmaf(e, f23.y, a3);
        z += e;
    }
    float iz = 1.f / (z + 1e-16f);
    float4 bv = *(const float4*)(b2 + lane * 4);
    int g = batch[n];
    float* o = out + (size_t)g * 128 + lane * 4;
    atomicAdd(o + 0, eluf(a0 * iz + bv.x));
    atomicAdd(o + 1, eluf(a1 * iz + bv.y));
    atomicAdd(o + 2, eluf(a2 * iz + bv.z));
    atomicAdd(o + 3, eluf(a3 * iz + bv.w));
}

__global__ void k_pool_div(float* __restrict__ out) {
    int g = blockIdx.x, tid = threadIdx.x;
    out[g * 128 + tid] /= fmaxf(g_cnt[g], 1.f);
}

// ---------------- launcher ----------------
extern "C" void kernel_launch(void* const* d_in, const int* in_sizes, int n_in,
                              void* d_out, int out_size) {
    const float* x       = (const float*)d_in[0];
    const int*   ei      = (const int*)d_in[1];
    const int*   batch   = (const int*)d_in[2];
    const float* W1      = (const float*)d_in[3];
    const float* a_src1  = (const float*)d_in[4];
    const float* a_dst1  = (const float*)d_in[5];
    const float* b1      = (const float*)d_in[6];
    const float* W2      = (const float*)d_in[7];
    const float* a_src2  = (const float*)d_in[8];
    const float* a_dst2  = (const float*)d_in[9];
    const float* b2      = (const float*)d_in[10];
    float* out = (float*)d_out;

    cudaFuncSetAttribute(k_gemm2_mma, cudaFuncAttributeMaxDynamicSharedMemorySize, 49152);

    k_init<<<(GG * 128 + 255) / 256, 256>>>(out);
    k_fill<<<(EE + 255) / 256, 256>>>(ei);
    k_cnt<<<(NN + 255) / 256, 256>>>(batch);

    k_wa<<<1, 128>>>(W1, a_src1, a_dst1);
    k_proj1<<<4096, 128>>>(x, W1);
    k_agg1<<<(NN + 7) / 8, 256>>>(b1);

    k_w2prep<<<512, 128>>>(W2);
    k_gemm2_mma<<<(NN + 127) / 128, 256, 49152>>>(a_src2, a_dst2);

    k_agg2<<<(NN + 7) / 8, 256>>>(b2, batch, out);
    k_pool_div<<<GG, 128>>>(out);
}

// round 6
// speedup vs baseline: 3.7877x; 1.3041x over previous
#include <cuda_runtime.h>
#include <cuda_bf16.h>
#include <cuda_fp16.h>
#include <cstdint>

#define NN 100000
#define EE 300000
#define GG 4000
#define CAP 32

// ---------------- scratch (device globals; no allocation) ----------------
__device__ __align__(16) __half g_h1h[NN * 512];          // layer1 features fp16, [n][c*4+h]
__device__ __align__(16) float g_as1[NN * 4];
__device__ __align__(16) float g_ad1[NN * 4];
__device__ __align__(16) __half g_o1h[NN * 512];          // layer1 output fp16 (GEMM A) [n][h*128+c]
__device__ __align__(16) __half g_w2t[128 * 512];         // W2^T fp16 [n=128][k=512]
__device__ __align__(16) __half g_h2h[NN * 128];          // layer2 projected features fp16
__device__ float g_as2[NN];
__device__ float g_ad2[NN];
__device__ float g_wa[9][8];                              // folded a_src1/a_dst1 through W1
__device__ int   g_deg[NN];
__device__ int   g_col[NN * CAP];
__device__ float g_cnt[GG];

__device__ __forceinline__ float lrelu(float x) { return x > 0.f ? x : 0.2f * x; }
__device__ __forceinline__ float eluf(float x)  { return x > 0.f ? x : (__expf(x) - 1.f); }

__device__ __forceinline__ uint32_t smem_to_u32(const void* p) {
    uint32_t a;
    asm("{ .reg .u64 t; cvta.to.shared.u64 t, %1; cvt.u32.u64 %0, t; }" : "=r"(a) : "l"(p));
    return a;
}

#define LDSM_X4(r0, r1, r2, r3, addr) \
    asm volatile("ldmatrix.sync.aligned.m8n8.x4.shared.b16 {%0,%1,%2,%3}, [%4];" \
        : "=r"(r0), "=r"(r1), "=r"(r2), "=r"(r3) : "r"(addr))

__device__ __forceinline__ void mma16816h(float* d, uint32_t a0, uint32_t a1, uint32_t a2,
                                          uint32_t a3, uint32_t b0, uint32_t b1) {
    asm volatile(
        "mma.sync.aligned.m16n8k16.row.col.f32.f16.f16.f32 "
        "{%0,%1,%2,%3}, {%4,%5,%6,%7}, {%8,%9}, {%0,%1,%2,%3};"
        : "+f"(d[0]), "+f"(d[1]), "+f"(d[2]), "+f"(d[3])
        : "r"(a0), "r"(a1), "r"(a2), "r"(a3), "r"(b0), "r"(b1));
}

// ---------------- init: zero out / deg / cnt ----------------
__global__ void k_init(float* __restrict__ out) {
    int i = blockIdx.x * blockDim.x + threadIdx.x;
    if (i < GG * 128) out[i] = 0.f;
    if (i < NN) g_deg[i] = 0;
    if (i < GG) g_cnt[i] = 0.f;
}

// ---------------- adjacency fill + per-graph counts (merged) ----------------
__global__ void k_fillcnt(const int* __restrict__ ei, const int* __restrict__ batch) {
    int i = blockIdx.x * blockDim.x + threadIdx.x;
    if (i < EE) {
        int s = ei[i], d = ei[EE + i];
        int p = atomicAdd(&g_deg[d], 1);
        if (p < CAP) g_col[d * CAP + p] = s;
    }
    if (i < NN) atomicAdd(&g_cnt[batch[i]], 1.f);
}

// ---------------- fold a_src1/a_dst1 through W1 (warp per output) ----------------
__global__ void k_wa(const float* __restrict__ W1, const float* __restrict__ a_src1,
                     const float* __restrict__ a_dst1) {
    int gw = blockIdx.x * 8 + (threadIdx.x >> 5);
    int lane = threadIdx.x & 31;
    if (gw >= 72) return;
    int k = gw / 8, q = gw % 8, h = q & 3;
    const float* a = (q >= 4) ? a_dst1 : a_src1;
    float s = 0.f;
#pragma unroll
    for (int c = lane; c < 128; c += 32)
        s = fmaf(__ldg(&W1[k * 512 + h * 128 + c]), __ldg(&a[h * 128 + c]), s);
#pragma unroll
    for (int o = 16; o > 0; o >>= 1) s += __shfl_down_sync(0xffffffffu, s, o);
    if (lane == 0) g_wa[k][q] = s;
}

// ---------------- layer 1 projection (sync-free, W in registers) ----------------
__global__ __launch_bounds__(128) void k_proj1(const float* __restrict__ x,
                                               const float* __restrict__ W1) {
    int tid = threadIdx.x, lane = tid & 31, w = tid >> 5;
    int c = w * 32 + lane;
    float wreg[9][4];
#pragma unroll
    for (int k = 0; k < 9; k++)
#pragma unroll
        for (int h = 0; h < 4; h++)
            wreg[k][h] = __ldg(&W1[k * 512 + h * 128 + c]);
    float war[9];
    if (w == 0 && lane < 8) {
#pragma unroll
        for (int k = 0; k < 9; k++) war[k] = g_wa[k][lane];
    }
    for (int n = blockIdx.x; n < NN; n += gridDim.x) {
        float xv = (lane < 9) ? __ldg(&x[n * 9 + lane]) : 0.f;
        float xr[9];
#pragma unroll
        for (int k = 0; k < 9; k++) xr[k] = __shfl_sync(0xffffffffu, xv, k);
        float v[4];
#pragma unroll
        for (int h = 0; h < 4; h++) {
            float s = 0.f;
#pragma unroll
            for (int k = 0; k < 9; k++) s = fmaf(xr[k], wreg[k][h], s);
            v[h] = s;
        }
        __half2 p0 = __floats2half2_rn(v[0], v[1]);
        __half2 p1 = __floats2half2_rn(v[2], v[3]);
        uint2 pk;
        pk.x = *(uint32_t*)&p0;
        pk.y = *(uint32_t*)&p1;
        *(uint2*)(g_h1h + (size_t)n * 512 + c * 4) = pk;
        if (w == 0 && lane < 8) {
            float s = 0.f;
#pragma unroll
            for (int k = 0; k < 9; k++) s = fmaf(xr[k], war[k], s);
            if (lane < 4) g_as1[n * 4 + lane] = s;
            else g_ad1[n * 4 + (lane - 4)] = s;
        }
    }
}

// ---------------- layer 1 aggregation: warp per node, uint4 gather, no max pass ----------------
// lane owns channels {2u, 2u+1} for u = lane and u = lane+32 (uint4 = 2 channels x 4 heads)
__global__ __launch_bounds__(256) void k_agg1(const float* __restrict__ b1) {
    int n = blockIdx.x * 8 + (threadIdx.x >> 5);
    if (n >= NN) return;
    int lane = threadIdx.x & 31;
    const float4* as4 = (const float4*)g_as1;
    float4 adv = ((const float4*)g_ad1)[n];
    float4 a0 = as4[n];
    float e0 = __expf(lrelu(a0.x + adv.x));
    float e1 = __expf(lrelu(a0.y + adv.y));
    float e2 = __expf(lrelu(a0.z + adv.z));
    float e3 = __expf(lrelu(a0.w + adv.w));
    float z0 = e0, z1 = e1, z2 = e2, z3 = e3;
    int deg = min(g_deg[n], CAP);
    const int* col = g_col + n * CAP;
    // acc[k][sub][h]
    float acc[2][2][4];
    {
        const uint4* hp = (const uint4*)(g_h1h + (size_t)n * 512);
#pragma unroll
        for (int k = 0; k < 2; k++) {
            uint4 q = hp[lane + 32 * k];
            float2 f0 = __half22float2(*(__half2*)&q.x);
            float2 f1 = __half22float2(*(__half2*)&q.y);
            float2 f2 = __half22float2(*(__half2*)&q.z);
            float2 f3 = __half22float2(*(__half2*)&q.w);
            acc[k][0][0] = e0 * f0.x; acc[k][0][1] = e1 * f0.y;
            acc[k][0][2] = e2 * f1.x; acc[k][0][3] = e3 * f1.y;
            acc[k][1][0] = e0 * f2.x; acc[k][1][1] = e1 * f2.y;
            acc[k][1][2] = e2 * f3.x; acc[k][1][3] = e3 * f3.y;
        }
    }
    for (int j = 0; j < deg; j++) {
        int s = col[j];
        float4 a = as4[s];
        float q0 = __expf(lrelu(a.x + adv.x));
        float q1 = __expf(lrelu(a.y + adv.y));
        float q2 = __expf(lrelu(a.z + adv.z));
        float q3 = __expf(lrelu(a.w + adv.w));
        const uint4* hp = (const uint4*)(g_h1h + (size_t)s * 512);
#pragma unroll
        for (int k = 0; k < 2; k++) {
            uint4 q = hp[lane + 32 * k];
            float2 f0 = __half22float2(*(__half2*)&q.x);
            float2 f1 = __half22float2(*(__half2*)&q.y);
            float2 f2 = __half22float2(*(__half2*)&q.z);
            float2 f3 = __half22float2(*(__half2*)&q.w);
            acc[k][0][0] = fmaf(q0, f0.x, acc[k][0][0]);
            acc[k][0][1] = fmaf(q1, f0.y, acc[k][0][1]);
            acc[k][0][2] = fmaf(q2, f1.x, acc[k][0][2]);
            acc[k][0][3] = fmaf(q3, f1.y, acc[k][0][3]);
            acc[k][1][0] = fmaf(q0, f2.x, acc[k][1][0]);
            acc[k][1][1] = fmaf(q1, f2.y, acc[k][1][1]);
            acc[k][1][2] = fmaf(q2, f3.x, acc[k][1][2]);
            acc[k][1][3] = fmaf(q3, f3.y, acc[k][1][3]);
        }
        z0 += q0; z1 += q1; z2 += q2; z3 += q3;
    }
    float iz[4];
    iz[0] = 1.f / (z0 + 1e-16f); iz[1] = 1.f / (z1 + 1e-16f);
    iz[2] = 1.f / (z2 + 1e-16f); iz[3] = 1.f / (z3 + 1e-16f);
#pragma unroll
    for (int k = 0; k < 2; k++)
#pragma unroll
        for (int sub = 0; sub < 2; sub++) {
            int c = 2 * (lane + 32 * k) + sub;
#pragma unroll
            for (int h = 0; h < 4; h++) {
                float v = eluf(acc[k][sub][h] * iz[h] + __ldg(&b1[h * 128 + c]));
                g_o1h[(size_t)n * 512 + h * 128 + c] = __float2half(v);
            }
        }
}

// ---------------- W2 transpose fp16 ----------------
__global__ void k_w2prep(const float* __restrict__ W2) {
    int k = blockIdx.x, n = threadIdx.x;
    g_w2t[n * 512 + k] = __float2half(W2[k * 128 + n]);
}

// ---------------- HMMA GEMM2 (fp16 single pass), fused alpha2, fp16 h2 ----------------
#define SWZC(rowIdx) (((rowIdx) & 7) << 4)

__global__ __launch_bounds__(256, 2) void k_gemm2_mma(const float* __restrict__ a_src2,
                                                      const float* __restrict__ a_dst2) {
    extern __shared__ char smem[];
    char* sA = smem;                  // 16 KB
    char* sB = smem + 16384;          // 16 KB
    uint32_t uA = smem_to_u32(sA);
    uint32_t uB = uA + 16384;

    int tid = threadIdx.x;
    int lane = tid & 31, wid = tid >> 5;
    int warpM = wid & 3, warpN = wid >> 2;
    int rb = warpM * 32, cb = warpN * 64;
    int m0 = blockIdx.x * 128;

    float acc[2][8][4];
#pragma unroll
    for (int i = 0; i < 2; i++)
#pragma unroll
        for (int j = 0; j < 8; j++)
#pragma unroll
            for (int q = 0; q < 4; q++) acc[i][j][q] = 0.f;

    int ldRow = tid >> 1;
    int ldPart = (tid & 1) * 4;
    int aRow = m0 + ldRow;
    bool aOk = aRow < NN;
    uint32_t ldSwc = SWZC(ldRow);
    uint32_t ldRowOff = ldRow * 128;

    int g = lane >> 3;
    int aFr0 = rb + (g & 1) * 8 + (lane & 7);
    uint32_t aKb = (uint32_t)((g >> 1) << 4);
    int bFr0 = cb + (g >> 1) * 8 + (lane & 7);
    uint32_t bKb = (uint32_t)((g & 1) << 4);

    for (int ch = 0; ch < 8; ch++) {
        __syncthreads();
        {
            uint4 zero = make_uint4(0, 0, 0, 0);
            const uint4* pA = (const uint4*)(g_o1h + (size_t)aRow * 512 + ch * 64);
            const uint4* pB = (const uint4*)(g_w2t + (size_t)ldRow * 512 + ch * 64);
#pragma unroll
            for (int i = 0; i < 4; i++) {
                uint32_t kb = (uint32_t)((ldPart + i) << 4);
                uint32_t off = ldRowOff + (kb ^ ldSwc);
                *(uint4*)(sA + off) = aOk ? pA[ldPart + i] : zero;
                *(uint4*)(sB + off) = pB[ldPart + i];
            }
        }
        __syncthreads();
#pragma unroll
        for (int kk = 0; kk < 4; kk++) {
            uint32_t kkb = (uint32_t)(kk << 5);
            uint32_t ah[2][4];
#pragma unroll
            for (int mf = 0; mf < 2; mf++) {
                int r = aFr0 + mf * 16;
                uint32_t off = (uint32_t)(r * 128) + ((kkb + aKb) ^ SWZC(r));
                LDSM_X4(ah[mf][0], ah[mf][1], ah[mf][2], ah[mf][3], uA + off);
            }
            uint32_t bh[4][4];
#pragma unroll
            for (int p = 0; p < 4; p++) {
                int r = bFr0 + p * 16;
                uint32_t off = (uint32_t)(r * 128) + ((kkb + bKb) ^ SWZC(r));
                LDSM_X4(bh[p][0], bh[p][1], bh[p][2], bh[p][3], uB + off);
            }
#pragma unroll
            for (int mf = 0; mf < 2; mf++)
#pragma unroll
                for (int p = 0; p < 4; p++) {
                    mma16816h(acc[mf][2 * p], ah[mf][0], ah[mf][1], ah[mf][2], ah[mf][3],
                              bh[p][0], bh[p][1]);
                    mma16816h(acc[mf][2 * p + 1], ah[mf][0], ah[mf][1], ah[mf][2], ah[mf][3],
                              bh[p][2], bh[p][3]);
                }
        }
    }
    __syncthreads();

    float* red = (float*)smem;
    if (tid < 256) red[tid] = 0.f;
    __syncthreads();

    float ps[2][2] = {{0.f, 0.f}, {0.f, 0.f}};
    float pd[2][2] = {{0.f, 0.f}, {0.f, 0.f}};
    int rq = lane >> 2;
    int cq = (lane & 3) * 2;
#pragma unroll
    for (int nf = 0; nf < 8; nf++) {
        int c = cb + nf * 8 + cq;
        float2 sv = __ldg((const float2*)(a_src2 + c));
        float2 dv = __ldg((const float2*)(a_dst2 + c));
#pragma unroll
        for (int mf = 0; mf < 2; mf++) {
            float* a = acc[mf][nf];
            ps[mf][0] = fmaf(a[0], sv.x, fmaf(a[1], sv.y, ps[mf][0]));
            ps[mf][1] = fmaf(a[2], sv.x, fmaf(a[3], sv.y, ps[mf][1]));
            pd[mf][0] = fmaf(a[0], dv.x, fmaf(a[1], dv.y, pd[mf][0]));
            pd[mf][1] = fmaf(a[2], dv.x, fmaf(a[3], dv.y, pd[mf][1]));
            int row0 = m0 + rb + mf * 16 + rq;
            if (row0 < NN) {
                __half2 hh = __floats2half2_rn(a[0], a[1]);
                *(__half2*)(g_h2h + (size_t)row0 * 128 + c) = hh;
            }
            if (row0 + 8 < NN) {
                __half2 hh = __floats2half2_rn(a[2], a[3]);
                *(__half2*)(g_h2h + (size_t)(row0 + 8) * 128 + c) = hh;
            }
        }
    }
#pragma unroll
    for (int mf = 0; mf < 2; mf++)
#pragma unroll
        for (int h = 0; h < 2; h++) {
#pragma unroll
            for (int o = 1; o <= 2; o <<= 1) {
                ps[mf][h] += __shfl_xor_sync(0xffffffffu, ps[mf][h], o);
                pd[mf][h] += __shfl_xor_sync(0xffffffffu, pd[mf][h], o);
            }
        }
    if ((lane & 3) == 0) {
#pragma unroll
        for (int mf = 0; mf < 2; mf++) {
            int lr = rb + mf * 16 + rq;
            atomicAdd(&red[lr], ps[mf][0]);
            atomicAdd(&red[lr + 8], ps[mf][1]);
            atomicAdd(&red[128 + lr], pd[mf][0]);
            atomicAdd(&red[128 + lr + 8], pd[mf][1]);
        }
    }
    __syncthreads();
    if (tid < 128) {
        int row = m0 + tid;
        if (row < NN) {
            g_as2[row] = red[tid];
            g_ad2[row] = red[128 + tid];
        }
    }
}

// ---------------- layer 2 aggregation (warp per node) + block-merged pool atomics ----------------
__global__ __launch_bounds__(256) void k_agg2(const float* __restrict__ b2,
                                              const int* __restrict__ batch,
                                              float* __restrict__ out) {
    __shared__ float sval[8][128];
    __shared__ int sg[8];
    int w = threadIdx.x >> 5, lane = threadIdx.x & 31;
    int n = blockIdx.x * 8 + w;
    bool valid = n < NN;
    if (valid) {
        float adn = g_ad2[n];
        float e = __expf(lrelu(g_as2[n] + adn));
        float z = e;
        int deg = min(g_deg[n], CAP);
        const int* col = g_col + n * CAP;
        float a0, a1, a2, a3;
        {
            uint2 q = *(const uint2*)(g_h2h + (size_t)n * 128 + lane * 4);
            float2 f01 = __half22float2(*(__half2*)&q.x);
            float2 f23 = __half22float2(*(__half2*)&q.y);
            a0 = e * f01.x; a1 = e * f01.y; a2 = e * f23.x; a3 = e * f23.y;
        }
        for (int j = 0; j < deg; j++) {
            int s = col[j];
            float ee = __expf(lrelu(g_as2[s] + adn));
            uint2 q = *(const uint2*)(g_h2h + (size_t)s * 128 + lane * 4);
            float2 f01 = __half22float2(*(__half2*)&q.x);
            float2 f23 = __half22float2(*(__half2*)&q.y);
            a0 = fmaf(ee, f01.x, a0);
            a1 = fmaf(ee, f01.y, a1);
            a2 = fmaf(ee, f23.x, a2);
            a3 = fmaf(ee, f23.y, a3);
            z += ee;
        }
        float iz = 1.f / (z + 1e-16f);
        float4 bv = *(const float4*)(b2 + lane * 4);
        sval[w][lane * 4 + 0] = eluf(a0 * iz + bv.x);
        sval[w][lane * 4 + 1] = eluf(a1 * iz + bv.y);
        sval[w][lane * 4 + 2] = eluf(a2 * iz + bv.z);
        sval[w][lane * 4 + 3] = eluf(a3 * iz + bv.w);
        if (lane == 0) sg[w] = batch[n];
    } else if (lane == 0) {
        sg[w] = -1;
    }
    __syncthreads();
    int t = threadIdx.x;
    if (t < 128) {
        float run = 0.f;
        int curg = -1;
#pragma unroll
        for (int w2 = 0; w2 < 8; w2++) {
            int gid = sg[w2];
            if (gid < 0) continue;
            if (gid != curg) {
                if (curg >= 0) atomicAdd(&out[(size_t)curg * 128 + t], run);
                curg = gid;
                run = 0.f;
            }
            run += sval[w2][t];
        }
        if (curg >= 0) atomicAdd(&out[(size_t)curg * 128 + t], run);
    }
}

__global__ void k_pool_div(float* __restrict__ out) {
    int g = blockIdx.x, tid = threadIdx.x;
    out[g * 128 + tid] /= fmaxf(g_cnt[g], 1.f);
}

// ---------------- launcher ----------------
extern "C" void kernel_launch(void* const* d_in, const int* in_sizes, int n_in,
                              void* d_out, int out_size) {
    const float* x       = (const float*)d_in[0];
    const int*   ei      = (const int*)d_in[1];
    const int*   batch   = (const int*)d_in[2];
    const float* W1      = (const float*)d_in[3];
    const float* a_src1  = (const float*)d_in[4];
    const float* a_dst1  = (const float*)d_in[5];
    const float* b1      = (const float*)d_in[6];
    const float* W2      = (const float*)d_in[7];
    const float* a_src2  = (const float*)d_in[8];
    const float* a_dst2  = (const float*)d_in[9];
    const float* b2      = (const float*)d_in[10];
    float* out = (float*)d_out;

    cudaFuncSetAttribute(k_gemm2_mma, cudaFuncAttributeMaxDynamicSharedMemorySize, 32768);

    k_init<<<(GG * 128 + 255) / 256, 256>>>(out);
    k_fillcnt<<<(EE + 255) / 256, 256>>>(ei, batch);

    k_wa<<<9, 256>>>(W1, a_src1, a_dst1);
    k_proj1<<<4096, 128>>>(x, W1);
    k_agg1<<<(NN + 7) / 8, 256>>>(b1);

    k_w2prep<<<512, 128>>>(W2);
    k_gemm2_mma<<<(NN + 127) / 128, 256, 32768>>>(a_src2, a_dst2);

    k_agg2<<<(NN + 7) / 8, 256>>>(b2, batch, out);
    k_pool_div<<<GG, 128>>>(out);
}

// round 7
// speedup vs baseline: 4.0472x; 1.0685x over previous
#include <cuda_runtime.h>
#include <cuda_bf16.h>
#include <cuda_fp16.h>
#include <cstdint>

#define NN 100000
#define EE 300000
#define GG 4000
#define CAP 32

// ---------------- scratch (device globals; no allocation) ----------------
__device__ __align__(16) __half g_a1[NN * 32];            // GEMM1 A: [x_hi(9), x_lo(9), x_hi(9), 0..]
__device__ __align__(16) __half g_w1t[512 * 32];          // GEMM1 B: [j=h*128+c][W_hi(9),W_hi(9),W_lo(9),0..]
__device__ __align__(16) __half g_h1h[NN * 512];          // layer1 features fp16, [n][h*128+c]
__device__ __align__(16) float g_as1[NN * 4];
__device__ __align__(16) float g_ad1[NN * 4];
__device__ __align__(16) __half g_o1h[NN * 512];          // layer1 output fp16 (GEMM2 A) [n][h*128+c]
__device__ __align__(16) __half g_w2t[128 * 512];         // W2^T fp16 [n=128][k=512]
__device__ __align__(16) __half g_h2h[NN * 128];          // layer2 projected features fp16
__device__ float g_as2[NN];
__device__ float g_ad2[NN];
__device__ float g_wa[9][8];                              // folded a_src1/a_dst1 through W1
__device__ int   g_deg[NN];
__device__ int   g_col[NN * CAP];
__device__ float g_cnt[GG];

__device__ __forceinline__ float lrelu(float x) { return x > 0.f ? x : 0.2f * x; }
__device__ __forceinline__ float eluf(float x)  { return x > 0.f ? x : (__expf(x) - 1.f); }

__device__ __forceinline__ uint32_t smem_to_u32(const void* p) {
    uint32_t a;
    asm("{ .reg .u64 t; cvta.to.shared.u64 t, %1; cvt.u32.u64 %0, t; }" : "=r"(a) : "l"(p));
    return a;
}

#define LDSM_X4(r0, r1, r2, r3, addr) \
    asm volatile("ldmatrix.sync.aligned.m8n8.x4.shared.b16 {%0,%1,%2,%3}, [%4];" \
        : "=r"(r0), "=r"(r1), "=r"(r2), "=r"(r3) : "r"(addr))

__device__ __forceinline__ void mma16816h(float* d, uint32_t a0, uint32_t a1, uint32_t a2,
                                          uint32_t a3, uint32_t b0, uint32_t b1) {
    asm volatile(
        "mma.sync.aligned.m16n8k16.row.col.f32.f16.f16.f32 "
        "{%0,%1,%2,%3}, {%4,%5,%6,%7}, {%8,%9}, {%0,%1,%2,%3};"
        : "+f"(d[0]), "+f"(d[1]), "+f"(d[2]), "+f"(d[3])
        : "r"(a0), "r"(a1), "r"(a2), "r"(a3), "r"(b0), "r"(b1));
}

#define SWZC(rowIdx) (((rowIdx) & 7) << 4)

// ---------------- init: zero out / deg / cnt ----------------
__global__ void k_init(float* __restrict__ out) {
    int i = blockIdx.x * blockDim.x + threadIdx.x;
    if (i < GG * 128) out[i] = 0.f;
    if (i < NN) g_deg[i] = 0;
    if (i < GG) g_cnt[i] = 0.f;
}

// ---------------- adjacency fill + per-graph counts ----------------
__global__ void k_fillcnt(const int* __restrict__ ei, const int* __restrict__ batch) {
    int i = blockIdx.x * blockDim.x + threadIdx.x;
    if (i < EE) {
        int s = ei[i], d = ei[EE + i];
        int p = atomicAdd(&g_deg[d], 1);
        if (p < CAP) g_col[d * CAP + p] = s;
    }
    if (i < NN) atomicAdd(&g_cnt[batch[i]], 1.f);
}

// ---------------- fold a_src1/a_dst1 through W1 (warp per output) ----------------
__global__ void k_wa(const float* __restrict__ W1, const float* __restrict__ a_src1,
                     const float* __restrict__ a_dst1) {
    int gw = blockIdx.x * 8 + (threadIdx.x >> 5);
    int lane = threadIdx.x & 31;
    if (gw >= 72) return;
    int k = gw / 8, q = gw % 8, h = q & 3;
    const float* a = (q >= 4) ? a_dst1 : a_src1;
    float s = 0.f;
#pragma unroll
    for (int c = lane; c < 128; c += 32)
        s = fmaf(__ldg(&W1[k * 512 + h * 128 + c]), __ldg(&a[h * 128 + c]), s);
#pragma unroll
    for (int o = 16; o > 0; o >>= 1) s += __shfl_down_sync(0xffffffffu, s, o);
    if (lane == 0) g_wa[k][q] = s;
}

// ---------------- GEMM1 B prep: g_w1t[j][32] ----------------
__global__ void k_w1prep(const float* __restrict__ W1) {
    int j = blockIdx.x, k = threadIdx.x;  // 512 blocks, 32 threads
    __half v = __float2half(0.f);
    if (k < 27) {
        int km = k % 9;
        float w = W1[km * 512 + j];
        __half hi = __float2half(w);
        v = (k < 18) ? hi : __float2half(w - __half2float(hi));
    }
    g_w1t[j * 32 + k] = v;
}

// ---------------- GEMM1 A prep + as1/ad1 (thread per node) ----------------
__global__ void k_prep1(const float* __restrict__ x) {
    int n = blockIdx.x * blockDim.x + threadIdx.x;
    if (n >= NN) return;
    float xv[9];
#pragma unroll
    for (int k = 0; k < 9; k++) xv[k] = __ldg(&x[n * 9 + k]);
    __half h16[32];
#pragma unroll
    for (int k = 0; k < 9; k++) {
        __half hi = __float2half(xv[k]);
        h16[k] = hi;
        h16[k + 9] = __float2half(xv[k] - __half2float(hi));
        h16[k + 18] = hi;
    }
#pragma unroll
    for (int k = 27; k < 32; k++) h16[k] = __float2half(0.f);
    uint4* dst = (uint4*)(g_a1 + (size_t)n * 32);
#pragma unroll
    for (int i = 0; i < 4; i++) dst[i] = ((uint4*)h16)[i];
    float s[8];
#pragma unroll
    for (int q = 0; q < 8; q++) {
        float v = 0.f;
#pragma unroll
        for (int k = 0; k < 9; k++) v = fmaf(xv[k], g_wa[k][q], v);
        s[q] = v;
    }
    ((float4*)g_as1)[n] = make_float4(s[0], s[1], s[2], s[3]);
    ((float4*)g_ad1)[n] = make_float4(s[4], s[5], s[6], s[7]);
}

// ---------------- HMMA GEMM1: h1 = A1[100000,32] @ W1T[512,32]^T ----------------
// grid (ceil(NN/128), 4); CTA computes 128 rows x 128 cols (n-block by).
__global__ __launch_bounds__(256, 2) void k_gemm1_mma() {
    extern __shared__ char smem[];
    char* sA = smem;              // 128 rows x 128B (64B used) = 16KB
    char* sB = smem + 16384;      // 16KB
    uint32_t uA = smem_to_u32(sA);
    uint32_t uB = uA + 16384;

    int tid = threadIdx.x;
    int lane = tid & 31, wid = tid >> 5;
    int warpM = wid & 3, warpN = wid >> 2;
    int rb = warpM * 32, cb = warpN * 64;
    int m0 = blockIdx.x * 128;
    int j0 = blockIdx.y * 128;

    // load tiles: threads 0-127 -> A rows, 128-255 -> B rows
    {
        int r = tid & 127;
        bool isA = tid < 128;
        uint4 zero = make_uint4(0, 0, 0, 0);
        const uint4* src;
        bool ok;
        if (isA) {
            int row = m0 + r;
            ok = row < NN;
            src = (const uint4*)(g_a1 + (size_t)(ok ? row : 0) * 32);
        } else {
            ok = true;
            src = (const uint4*)(g_w1t + (size_t)(j0 + r) * 32);
        }
        char* base = isA ? sA : sB;
#pragma unroll
        for (int i = 0; i < 4; i++) {
            uint32_t off = (uint32_t)(r * 128) + (((uint32_t)(i << 4)) ^ SWZC(r));
            *(uint4*)(base + off) = ok ? src[i] : zero;
        }
    }
    __syncthreads();

    float acc[2][8][4];
#pragma unroll
    for (int i = 0; i < 2; i++)
#pragma unroll
        for (int j = 0; j < 8; j++)
#pragma unroll
            for (int q = 0; q < 4; q++) acc[i][j][q] = 0.f;

    int g = lane >> 3;
    int aFr0 = rb + (g & 1) * 8 + (lane & 7);
    uint32_t aKb = (uint32_t)((g >> 1) << 4);
    int bFr0 = cb + (g >> 1) * 8 + (lane & 7);
    uint32_t bKb = (uint32_t)((g & 1) << 4);

#pragma unroll
    for (int kk = 0; kk < 2; kk++) {
        uint32_t kkb = (uint32_t)(kk << 5);
        uint32_t ah[2][4];
#pragma unroll
        for (int mf = 0; mf < 2; mf++) {
            int r = aFr0 + mf * 16;
            uint32_t off = (uint32_t)(r * 128) + ((kkb + aKb) ^ SWZC(r));
            LDSM_X4(ah[mf][0], ah[mf][1], ah[mf][2], ah[mf][3], uA + off);
        }
        uint32_t bh[4][4];
#pragma unroll
        for (int p = 0; p < 4; p++) {
            int r = bFr0 + p * 16;
            uint32_t off = (uint32_t)(r * 128) + ((kkb + bKb) ^ SWZC(r));
            LDSM_X4(bh[p][0], bh[p][1], bh[p][2], bh[p][3], uB + off);
        }
#pragma unroll
        for (int mf = 0; mf < 2; mf++)
#pragma unroll
            for (int p = 0; p < 4; p++) {
                mma16816h(acc[mf][2 * p], ah[mf][0], ah[mf][1], ah[mf][2], ah[mf][3],
                          bh[p][0], bh[p][1]);
                mma16816h(acc[mf][2 * p + 1], ah[mf][0], ah[mf][1], ah[mf][2], ah[mf][3],
                          bh[p][2], bh[p][3]);
            }
    }

    // epilogue: store h1 fp16 [n][j]
    int rq = lane >> 2;
    int cq = (lane & 3) * 2;
#pragma unroll
    for (int nf = 0; nf < 8; nf++) {
        int jg = j0 + cb + nf * 8 + cq;
#pragma unroll
        for (int mf = 0; mf < 2; mf++) {
            float* a = acc[mf][nf];
            int row0 = m0 + rb + mf * 16 + rq;
            if (row0 < NN) {
                __half2 hh = __floats2half2_rn(a[0], a[1]);
                *(__half2*)(g_h1h + (size_t)row0 * 512 + jg) = hh;
            }
            if (row0 + 8 < NN) {
                __half2 hh = __floats2half2_rn(a[2], a[3]);
                *(__half2*)(g_h1h + (size_t)(row0 + 8) * 512 + jg) = hh;
            }
        }
    }
}

// ---------------- layer 1 aggregation: warp per node, [n][h*128+c] layout ----------------
__global__ __launch_bounds__(256) void k_agg1(const float* __restrict__ b1) {
    int n = blockIdx.x * 8 + (threadIdx.x >> 5);
    if (n >= NN) return;
    int lane = threadIdx.x & 31;
    bool hiHalf = lane >= 16;        // uint4 idx u: head = u>>4
    const float4* as4 = (const float4*)g_as1;
    float4 adv = ((const float4*)g_ad1)[n];
    float4 a0 = as4[n];
    float q0 = __expf(lrelu(a0.x + adv.x));
    float q1 = __expf(lrelu(a0.y + adv.y));
    float q2 = __expf(lrelu(a0.z + adv.z));
    float q3 = __expf(lrelu(a0.w + adv.w));
    float z0 = q0, z1 = q1, z2 = q2, z3 = q3;
    float e0 = hiHalf ? q1 : q0;     // weight for k=0 group (heads 0/1)
    float e1 = hiHalf ? q3 : q2;     // weight for k=1 group (heads 2/3)
    float acc[2][8];
    {
        const uint4* hp = (const uint4*)(g_h1h + (size_t)n * 512);
        uint4 qa = hp[lane];
        uint4 qb = hp[lane + 32];
        const __half2* pa = (const __half2*)&qa;
        const __half2* pb = (const __half2*)&qb;
#pragma unroll
        for (int t = 0; t < 4; t++) {
            float2 fa = __half22float2(pa[t]);
            float2 fb = __half22float2(pb[t]);
            acc[0][2 * t] = e0 * fa.x;
            acc[0][2 * t + 1] = e0 * fa.y;
            acc[1][2 * t] = e1 * fb.x;
            acc[1][2 * t + 1] = e1 * fb.y;
        }
    }
    int deg = min(g_deg[n], CAP);
    const int* col = g_col + n * CAP;
    for (int j = 0; j < deg; j++) {
        int s = col[j];
        float4 a = as4[s];
        float p0 = __expf(lrelu(a.x + adv.x));
        float p1 = __expf(lrelu(a.y + adv.y));
        float p2 = __expf(lrelu(a.z + adv.z));
        float p3 = __expf(lrelu(a.w + adv.w));
        float w0 = hiHalf ? p1 : p0;
        float w1 = hiHalf ? p3 : p2;
        const uint4* hp = (const uint4*)(g_h1h + (size_t)s * 512);
        uint4 qa = hp[lane];
        uint4 qb = hp[lane + 32];
        const __half2* pa = (const __half2*)&qa;
        const __half2* pb = (const __half2*)&qb;
#pragma unroll
        for (int t = 0; t < 4; t++) {
            float2 fa = __half22float2(pa[t]);
            float2 fb = __half22float2(pb[t]);
            acc[0][2 * t] = fmaf(w0, fa.x, acc[0][2 * t]);
            acc[0][2 * t + 1] = fmaf(w0, fa.y, acc[0][2 * t + 1]);
            acc[1][2 * t] = fmaf(w1, fb.x, acc[1][2 * t]);
            acc[1][2 * t + 1] = fmaf(w1, fb.y, acc[1][2 * t + 1]);
        }
        z0 += p0; z1 += p1; z2 += p2; z3 += p3;
    }
    float iz0 = 1.f / (z0 + 1e-16f), iz1 = 1.f / (z1 + 1e-16f);
    float iz2 = 1.f / (z2 + 1e-16f), iz3 = 1.f / (z3 + 1e-16f);
    float izk0 = hiHalf ? iz1 : iz0;
    float izk1 = hiHalf ? iz3 : iz2;
#pragma unroll
    for (int k = 0; k < 2; k++) {
        int u = lane + 32 * k;
        int j0 = u * 8;
        float izk = k == 0 ? izk0 : izk1;
        float4 bv0 = __ldg((const float4*)(b1 + j0));
        float4 bv1 = __ldg((const float4*)(b1 + j0 + 4));
        float v[8];
        v[0] = eluf(acc[k][0] * izk + bv0.x);
        v[1] = eluf(acc[k][1] * izk + bv0.y);
        v[2] = eluf(acc[k][2] * izk + bv0.z);
        v[3] = eluf(acc[k][3] * izk + bv0.w);
        v[4] = eluf(acc[k][4] * izk + bv1.x);
        v[5] = eluf(acc[k][5] * izk + bv1.y);
        v[6] = eluf(acc[k][6] * izk + bv1.z);
        v[7] = eluf(acc[k][7] * izk + bv1.w);
        uint4 pk;
        __half2 h0 = __floats2half2_rn(v[0], v[1]);
        __half2 h1 = __floats2half2_rn(v[2], v[3]);
        __half2 h2 = __floats2half2_rn(v[4], v[5]);
        __half2 h3 = __floats2half2_rn(v[6], v[7]);
        pk.x = *(uint32_t*)&h0; pk.y = *(uint32_t*)&h1;
        pk.z = *(uint32_t*)&h2; pk.w = *(uint32_t*)&h3;
        *(uint4*)(g_o1h + (size_t)n * 512 + j0) = pk;
    }
}

// ---------------- W2 transpose fp16 ----------------
__global__ void k_w2prep(const float* __restrict__ W2) {
    int k = blockIdx.x, n = threadIdx.x;
    g_w2t[n * 512 + k] = __float2half(W2[k * 128 + n]);
}

// ---------------- HMMA GEMM2 (fp16 single pass), fused alpha2, fp16 h2 ----------------
__global__ __launch_bounds__(256, 2) void k_gemm2_mma(const float* __restrict__ a_src2,
                                                      const float* __restrict__ a_dst2) {
    extern __shared__ char smem[];
    char* sA = smem;
    char* sB = smem + 16384;
    uint32_t uA = smem_to_u32(sA);
    uint32_t uB = uA + 16384;

    int tid = threadIdx.x;
    int lane = tid & 31, wid = tid >> 5;
    int warpM = wid & 3, warpN = wid >> 2;
    int rb = warpM * 32, cb = warpN * 64;
    int m0 = blockIdx.x * 128;

    float acc[2][8][4];
#pragma unroll
    for (int i = 0; i < 2; i++)
#pragma unroll
        for (int j = 0; j < 8; j++)
#pragma unroll
            for (int q = 0; q < 4; q++) acc[i][j][q] = 0.f;

    int ldRow = tid >> 1;
    int ldPart = (tid & 1) * 4;
    int aRow = m0 + ldRow;
    bool aOk = aRow < NN;
    uint32_t ldSwc = SWZC(ldRow);
    uint32_t ldRowOff = ldRow * 128;

    int g = lane >> 3;
    int aFr0 = rb + (g & 1) * 8 + (lane & 7);
    uint32_t aKb = (uint32_t)((g >> 1) << 4);
    int bFr0 = cb + (g >> 1) * 8 + (lane & 7);
    uint32_t bKb = (uint32_t)((g & 1) << 4);

    for (int ch = 0; ch < 8; ch++) {
        __syncthreads();
        {
            uint4 zero = make_uint4(0, 0, 0, 0);
            const uint4* pA = (const uint4*)(g_o1h + (size_t)aRow * 512 + ch * 64);
            const uint4* pB = (const uint4*)(g_w2t + (size_t)ldRow * 512 + ch * 64);
#pragma unroll
            for (int i = 0; i < 4; i++) {
                uint32_t kb = (uint32_t)((ldPart + i) << 4);
                uint32_t off = ldRowOff + (kb ^ ldSwc);
                *(uint4*)(sA + off) = aOk ? pA[ldPart + i] : zero;
                *(uint4*)(sB + off) = pB[ldPart + i];
            }
        }
        __syncthreads();
#pragma unroll
        for (int kk = 0; kk < 4; kk++) {
            uint32_t kkb = (uint32_t)(kk << 5);
            uint32_t ah[2][4];
#pragma unroll
            for (int mf = 0; mf < 2; mf++) {
                int r = aFr0 + mf * 16;
                uint32_t off = (uint32_t)(r * 128) + ((kkb + aKb) ^ SWZC(r));
                LDSM_X4(ah[mf][0], ah[mf][1], ah[mf][2], ah[mf][3], uA + off);
            }
            uint32_t bh[4][4];
#pragma unroll
            for (int p = 0; p < 4; p++) {
                int r = bFr0 + p * 16;
                uint32_t off = (uint32_t)(r * 128) + ((kkb + bKb) ^ SWZC(r));
                LDSM_X4(bh[p][0], bh[p][1], bh[p][2], bh[p][3], uB + off);
            }
#pragma unroll
            for (int mf = 0; mf < 2; mf++)
#pragma unroll
                for (int p = 0; p < 4; p++) {
                    mma16816h(acc[mf][2 * p], ah[mf][0], ah[mf][1], ah[mf][2], ah[mf][3],
                              bh[p][0], bh[p][1]);
                    mma16816h(acc[mf][2 * p + 1], ah[mf][0], ah[mf][1], ah[mf][2], ah[mf][3],
                              bh[p][2], bh[p][3]);
                }
        }
    }
    __syncthreads();

    float* red = (float*)smem;
    if (tid < 256) red[tid] = 0.f;
    __syncthreads();

    float ps[2][2] = {{0.f, 0.f}, {0.f, 0.f}};
    float pd[2][2] = {{0.f, 0.f}, {0.f, 0.f}};
    int rq = lane >> 2;
    int cq = (lane & 3) * 2;
#pragma unroll
    for (int nf = 0; nf < 8; nf++) {
        int c = cb + nf * 8 + cq;
        float2 sv = __ldg((const float2*)(a_src2 + c));
        float2 dv = __ldg((const float2*)(a_dst2 + c));
#pragma unroll
        for (int mf = 0; mf < 2; mf++) {
            float* a = acc[mf][nf];
            ps[mf][0] = fmaf(a[0], sv.x, fmaf(a[1], sv.y, ps[mf][0]));
            ps[mf][1] = fmaf(a[2], sv.x, fmaf(a[3], sv.y, ps[mf][1]));
            pd[mf][0] = fmaf(a[0], dv.x, fmaf(a[1], dv.y, pd[mf][0]));
            pd[mf][1] = fmaf(a[2], dv.x, fmaf(a[3], dv.y, pd[mf][1]));
            int row0 = m0 + rb + mf * 16 + rq;
            if (row0 < NN) {
                __half2 hh = __floats2half2_rn(a[0], a[1]);
                *(__half2*)(g_h2h + (size_t)row0 * 128 + c) = hh;
            }
            if (row0 + 8 < NN) {
                __half2 hh = __floats2half2_rn(a[2], a[3]);
                *(__half2*)(g_h2h + (size_t)(row0 + 8) * 128 + c) = hh;
            }
        }
    }
#pragma unroll
    for (int mf = 0; mf < 2; mf++)
#pragma unroll
        for (int h = 0; h < 2; h++) {
#pragma unroll
            for (int o = 1; o <= 2; o <<= 1) {
                ps[mf][h] += __shfl_xor_sync(0xffffffffu, ps[mf][h], o);
                pd[mf][h] += __shfl_xor_sync(0xffffffffu, pd[mf][h], o);
            }
        }
    if ((lane & 3) == 0) {
#pragma unroll
        for (int mf = 0; mf < 2; mf++) {
            int lr = rb + mf * 16 + rq;
            atomicAdd(&red[lr], ps[mf][0]);
            atomicAdd(&red[lr + 8], ps[mf][1]);
            atomicAdd(&red[128 + lr], pd[mf][0]);
            atomicAdd(&red[128 + lr + 8], pd[mf][1]);
        }
    }
    __syncthreads();
    if (tid < 128) {
        int row = m0 + tid;
        if (row < NN) {
            g_as2[row] = red[tid];
            g_ad2[row] = red[128 + tid];
        }
    }
}

// ---------------- layer 2 aggregation + block-merged pool atomics ----------------
__global__ __launch_bounds__(256) void k_agg2(const float* __restrict__ b2,
                                              const int* __restrict__ batch,
                                              float* __restrict__ out) {
    __shared__ float sval[8][128];
    __shared__ int sg[8];
    int w = threadIdx.x >> 5, lane = threadIdx.x & 31;
    int n = blockIdx.x * 8 + w;
    bool valid = n < NN;
    if (valid) {
        float adn = g_ad2[n];
        float e = __expf(lrelu(g_as2[n] + adn));
        float z = e;
        int deg = min(g_deg[n], CAP);
        const int* col = g_col + n * CAP;
        float a0, a1, a2, a3;
        {
            uint2 q = *(const uint2*)(g_h2h + (size_t)n * 128 + lane * 4);
            float2 f01 = __half22float2(*(__half2*)&q.x);
            float2 f23 = __half22float2(*(__half2*)&q.y);
            a0 = e * f01.x; a1 = e * f01.y; a2 = e * f23.x; a3 = e * f23.y;
        }
        for (int j = 0; j < deg; j++) {
            int s = col[j];
            float ee = __expf(lrelu(g_as2[s] + adn));
            uint2 q = *(const uint2*)(g_h2h + (size_t)s * 128 + lane * 4);
            float2 f01 = __half22float2(*(__half2*)&q.x);
            float2 f23 = __half22float2(*(__half2*)&q.y);
            a0 = fmaf(ee, f01.x, a0);
            a1 = fmaf(ee, f01.y, a1);
            a2 = fmaf(ee, f23.x, a2);
            a3 = fmaf(ee, f23.y, a3);
            z += ee;
        }
        float iz = 1.f / (z + 1e-16f);
        float4 bv = *(const float4*)(b2 + lane * 4);
        sval[w][lane * 4 + 0] = eluf(a0 * iz + bv.x);
        sval[w][lane * 4 + 1] = eluf(a1 * iz + bv.y);
        sval[w][lane * 4 + 2] = eluf(a2 * iz + bv.z);
        sval[w][lane * 4 + 3] = eluf(a3 * iz + bv.w);
        if (lane == 0) sg[w] = batch[n];
    } else if (lane == 0) {
        sg[w] = -1;
    }
    __syncthreads();
    int t = threadIdx.x;
    if (t < 128) {
        float run = 0.f;
        int curg = -1;
#pragma unroll
        for (int w2 = 0; w2 < 8; w2++) {
            int gid = sg[w2];
            if (gid < 0) continue;
            if (gid != curg) {
                if (curg >= 0) atomicAdd(&out[(size_t)curg * 128 + t], run);
                curg = gid;
                run = 0.f;
            }
            run += sval[w2][t];
        }
        if (curg >= 0) atomicAdd(&out[(size_t)curg * 128 + t], run);
    }
}

__global__ void k_pool_div(float* __restrict__ out) {
    int g = blockIdx.x, tid = threadIdx.x;
    out[g * 128 + tid] /= fmaxf(g_cnt[g], 1.f);
}

// ---------------- launcher ----------------
extern "C" void kernel_launch(void* const* d_in, const int* in_sizes, int n_in,
                              void* d_out, int out_size) {
    const float* x       = (const float*)d_in[0];
    const int*   ei      = (const int*)d_in[1];
    const int*   batch   = (const int*)d_in[2];
    const float* W1      = (const float*)d_in[3];
    const float* a_src1  = (const float*)d_in[4];
    const float* a_dst1  = (const float*)d_in[5];
    const float* b1      = (const float*)d_in[6];
    const float* W2      = (const float*)d_in[7];
    const float* a_src2  = (const float*)d_in[8];
    const float* a_dst2  = (const float*)d_in[9];
    const float* b2      = (const float*)d_in[10];
    float* out = (float*)d_out;

    cudaFuncSetAttribute(k_gemm1_mma, cudaFuncAttributeMaxDynamicSharedMemorySize, 32768);
    cudaFuncSetAttribute(k_gemm2_mma, cudaFuncAttributeMaxDynamicSharedMemorySize, 32768);

    k_init<<<(GG * 128 + 255) / 256, 256>>>(out);
    k_fillcnt<<<(EE + 255) / 256, 256>>>(ei, batch);

    k_wa<<<9, 256>>>(W1, a_src1, a_dst1);
    k_w1prep<<<512, 32>>>(W1);
    k_prep1<<<(NN + 255) / 256, 256>>>(x);
    {
        dim3 grid((NN + 127) / 128, 4);
        k_gemm1_mma<<<grid, 256, 32768>>>();
    }
    k_agg1<<<(NN + 7) / 8, 256>>>(b1);

    k_w2prep<<<512, 128>>>(W2);
    k_gemm2_mma<<<(NN + 127) / 128, 256, 32768>>>(a_src2, a_dst2);

    k_agg2<<<(NN + 7) / 8, 256>>>(b2, batch, out);
    k_pool_div<<<GG, 128>>>(out);
}